// round 1
// baseline (speedup 1.0000x reference)
#include <cuda_runtime.h>
#include <cuda_bf16.h>
#include <math.h>

// ---------------- problem constants ----------------
#define BATCH 8
#define NN    512
#define DIN   64
#define HH    8
#define FF    128
#define LL    2
#define NEGV  (-9e15f)

// ---------------- scratch (device globals; no allocs) ----------------
__device__ float g_h    [BATCH * NN * FF];            // current features
__device__ float g_hh   [BATCH * HH * NN * FF];       // per-head projections
__device__ float g_att  [BATCH * HH * NN * NN];       // multi-head attention
__device__ float g_multi[BATCH * NN * HH * FF];       // concat(heads) after ELU
__device__ float g_h2   [BATCH * NN * FF];            // out-proj features
__device__ float g_att2 [BATCH * NN * NN];            // single-head attention
__device__ float g_out  [BATCH * NN * FF];            // single-head output
__device__ float g_s1   [BATCH * HH * NN];
__device__ float g_s2   [BATCH * HH * NN];
__device__ float g_t1   [BATCH * NN];
__device__ float g_t2   [BATCH * NN];

// ---------------- reductions (blockDim.x == 128) ----------------
__device__ __forceinline__ float warpSum(float v) {
#pragma unroll
    for (int o = 16; o > 0; o >>= 1) v += __shfl_xor_sync(0xffffffffu, v, o);
    return v;
}
__device__ __forceinline__ float warpMax(float v) {
#pragma unroll
    for (int o = 16; o > 0; o >>= 1) v = fmaxf(v, __shfl_xor_sync(0xffffffffu, v, o));
    return v;
}
__device__ __forceinline__ float blockSum128(float v) {
    __shared__ float sh[4];
    v = warpSum(v);
    __syncthreads();
    if ((threadIdx.x & 31) == 0) sh[threadIdx.x >> 5] = v;
    __syncthreads();
    return sh[0] + sh[1] + sh[2] + sh[3];
}
__device__ __forceinline__ float blockMax128(float v) {
    __shared__ float sh[4];
    v = warpMax(v);
    __syncthreads();
    if ((threadIdx.x & 31) == 0) sh[threadIdx.x >> 5] = v;
    __syncthreads();
    return fmaxf(fmaxf(sh[0], sh[1]), fmaxf(sh[2], sh[3]));
}

// ---------------- input projection: h = relu(x @ Wp + bp) ----------------
__global__ void k_proj(const float* __restrict__ x, const float* __restrict__ Wp,
                       const float* __restrict__ bp, float* __restrict__ h) {
    __shared__ float xs[DIN];
    const int row = blockIdx.x;             // 0..B*N-1
    const int t = threadIdx.x;              // 0..127 (f)
    if (t < DIN) xs[t] = x[(long)row * DIN + t];
    __syncthreads();
    float acc = bp[t];
#pragma unroll
    for (int i = 0; i < DIN; i++) acc = fmaf(xs[i], Wp[i * FF + t], acc);
    h[(long)row * FF + t] = fmaxf(acc, 0.f);
}

// ---------------- generic register-tiled GEMM, N fixed = 128 ----------------
// C[M,128] = A[M,K] @ B[K,128], row-major. Batch z decomposed as (b = z/Hb, h = z%Hb).
// epi: 0 = none, 1 = ELU.
#define BM 64
#define BN 128
#define BK 16
#define TM 8
#define TN 4
__global__ __launch_bounds__(256, 2)
void k_gemm(const float* __restrict__ A, const float* __restrict__ B, float* __restrict__ C,
            int M, int K,
            long long sAb, long long sAh,
            long long sBb, long long sBh,
            long long sCb, long long sCh,
            int Hb, int ldc, int epi) {
    const int z = blockIdx.z;
    const int bz = z / Hb, hz = z % Hb;
    A += bz * sAb + hz * sAh;
    B += bz * sBb + hz * sBh;
    C += bz * sCb + hz * sCh;
    const int bm = blockIdx.y * BM;

    __shared__ float As[BK][BM];
    __shared__ float Bs[BK][BN];

    const int tid = threadIdx.x;       // 0..255
    const int tx = tid & 31;           // n-group
    const int ty = tid >> 5;           // m-group (0..7)

    float acc[TM][TN];
#pragma unroll
    for (int i = 0; i < TM; i++)
#pragma unroll
        for (int j = 0; j < TN; j++) acc[i][j] = 0.f;

    for (int k0 = 0; k0 < K; k0 += BK) {
        // A tile: 64 x 16, transposed into As[k][m]
        {
            const int m = tid >> 2;
            const int kk = (tid & 3) * 4;
            const float4 av = *(const float4*)(A + (long)(bm + m) * K + k0 + kk);
            As[kk + 0][m] = av.x;
            As[kk + 1][m] = av.y;
            As[kk + 2][m] = av.z;
            As[kk + 3][m] = av.w;
        }
        // B tile: 16 x 128
        {
            const int r = tid >> 5;
            const int c = (tid & 31) * 4;
            *(float4*)&Bs[r][c]     = *(const float4*)(B + (long)(k0 + r) * BN + c);
            *(float4*)&Bs[r + 8][c] = *(const float4*)(B + (long)(k0 + r + 8) * BN + c);
        }
        __syncthreads();
#pragma unroll
        for (int k = 0; k < BK; k++) {
            const float4 a0 = *(const float4*)&As[k][ty * TM];
            const float4 a1 = *(const float4*)&As[k][ty * TM + 4];
            const float4 bv = *(const float4*)&Bs[k][tx * TN];
            const float a[TM] = {a0.x, a0.y, a0.z, a0.w, a1.x, a1.y, a1.z, a1.w};
            const float bb[TN] = {bv.x, bv.y, bv.z, bv.w};
#pragma unroll
            for (int i = 0; i < TM; i++)
#pragma unroll
                for (int j = 0; j < TN; j++)
                    acc[i][j] = fmaf(a[i], bb[j], acc[i][j]);
        }
        __syncthreads();
    }

    const int row0 = bm + ty * TM;
    const int col = tx * TN;
#pragma unroll
    for (int i = 0; i < TM; i++) {
        float4 r;
        if (epi == 1) {
            r.x = acc[i][0] > 0.f ? acc[i][0] : (__expf(acc[i][0]) - 1.f);
            r.y = acc[i][1] > 0.f ? acc[i][1] : (__expf(acc[i][1]) - 1.f);
            r.z = acc[i][2] > 0.f ? acc[i][2] : (__expf(acc[i][2]) - 1.f);
            r.w = acc[i][3] > 0.f ? acc[i][3] : (__expf(acc[i][3]) - 1.f);
        } else {
            r = make_float4(acc[i][0], acc[i][1], acc[i][2], acc[i][3]);
        }
        *(float4*)(C + (long)(row0 + i) * ldc + col) = r;
    }
}

// ---------------- attention score vectors: s1/s2 = hh . a ----------------
// grid (N, H, B), 128 threads
__global__ void k_svec(const float* __restrict__ hh, const float* __restrict__ a,
                       float* __restrict__ s1, float* __restrict__ s2, int Hb) {
    const int n = blockIdx.x, h = blockIdx.y, b = blockIdx.z;
    const int t = threadIdx.x;
    const float v = hh[(((long)b * Hb + h) * NN + n) * FF + t];
    const float* av = a + (long)h * (2 * FF);
    float p1 = v * av[t];
    float p2 = v * av[FF + t];
    p1 = blockSum128(p1);
    p2 = blockSum128(p2);
    if (t == 0) {
        const long idx = ((long)b * Hb + h) * NN + n;
        s1[idx] = p1;
        s2[idx] = p2;
    }
}

// ---------------- masked leaky-relu softmax row ----------------
// grid (N, H, B), 128 threads, 4 m's per thread
__global__ void k_softmax(const int* __restrict__ adj, const float* __restrict__ s1,
                          const float* __restrict__ s2, float* __restrict__ att, int Hb) {
    const int n = blockIdx.x, h = blockIdx.y, b = blockIdx.z;
    const int t = threadIdx.x;
    const int* adjrow = adj + ((long)b * NN + n) * NN;
    const float* s2row = s2 + ((long)b * Hb + h) * NN;
    const float s1v = s1[((long)b * Hb + h) * NN + n];
    float* arow = att + (((long)b * Hb + h) * NN + n) * NN;

    float v[4];
    float mx = -INFINITY;
#pragma unroll
    for (int j = 0; j < 4; j++) {
        const int m = t + j * 128;
        float e = s1v + s2row[m];
        e = e > 0.f ? e : 0.2f * e;
        v[j] = (adjrow[m] > 0) ? e : NEGV;
        mx = fmaxf(mx, v[j]);
    }
    mx = blockMax128(mx);
    float sum = 0.f;
#pragma unroll
    for (int j = 0; j < 4; j++) {
        v[j] = __expf(v[j] - mx);   // masked lanes underflow to exactly 0
        sum += v[j];
    }
    sum = blockSum128(sum);
    const float inv = 1.f / sum;
#pragma unroll
    for (int j = 0; j < 4; j++) arow[t + j * 128] = v[j] * inv;
}

// ---------------- residual + layernorm (+ optional relu) ----------------
__global__ void k_lnorm(const float* __restrict__ o, const float* __restrict__ res,
                        const float* __restrict__ g, const float* __restrict__ bb,
                        float* __restrict__ dst, int do_relu) {
    const int row = blockIdx.x;
    const int t = threadIdx.x;
    const float y = o[(long)row * FF + t] + res[(long)row * FF + t];
    const float mu = blockSum128(y) * (1.f / FF);
    const float d = y - mu;
    const float var = blockSum128(d * d) * (1.f / FF);
    float r = d * rsqrtf(var + 1e-5f) * g[t] + bb[t];
    if (do_relu) r = fmaxf(r, 0.f);
    dst[(long)row * FF + t] = r;
}

// ---------------- host orchestration ----------------
extern "C" void kernel_launch(void* const* d_in, const int* in_sizes, int n_in,
                              void* d_out, int out_size) {
    (void)in_sizes; (void)n_in; (void)out_size;
    const float* x       = (const float*)d_in[0];
    const int*   adj     = (const int*)  d_in[1];
    const float* Wp      = (const float*)d_in[2];
    const float* bp      = (const float*)d_in[3];
    const float* W_heads = (const float*)d_in[4];
    const float* a_heads = (const float*)d_in[5];
    const float* W_out   = (const float*)d_in[6];
    const float* a_out   = (const float*)d_in[7];
    const float* ln_g    = (const float*)d_in[8];
    const float* ln_b    = (const float*)d_in[9];
    float* out = (float*)d_out;

    float *p_h, *p_hh, *p_att, *p_multi, *p_h2, *p_att2, *p_out;
    float *p_s1, *p_s2, *p_t1, *p_t2;
    cudaGetSymbolAddress((void**)&p_h, g_h);
    cudaGetSymbolAddress((void**)&p_hh, g_hh);
    cudaGetSymbolAddress((void**)&p_att, g_att);
    cudaGetSymbolAddress((void**)&p_multi, g_multi);
    cudaGetSymbolAddress((void**)&p_h2, g_h2);
    cudaGetSymbolAddress((void**)&p_att2, g_att2);
    cudaGetSymbolAddress((void**)&p_out, g_out);
    cudaGetSymbolAddress((void**)&p_s1, g_s1);
    cudaGetSymbolAddress((void**)&p_s2, g_s2);
    cudaGetSymbolAddress((void**)&p_t1, g_t1);
    cudaGetSymbolAddress((void**)&p_t2, g_t2);

    // input projection
    k_proj<<<BATCH * NN, 128>>>(x, Wp, bp, p_h);

    for (int l = 0; l < LL; l++) {
        // 1) per-head projection: hh[b,h] = h[b] @ W_heads[l,h]
        k_gemm<<<dim3(1, NN / BM, BATCH * HH), 256>>>(
            p_h, W_heads + (long)l * HH * FF * FF, p_hh,
            NN, FF,
            (long long)NN * FF, 0,
            0, (long long)FF * FF,
            (long long)HH * NN * FF, (long long)NN * FF,
            HH, FF, 0);

        // 2) attention score vectors
        k_svec<<<dim3(NN, HH, BATCH), 128>>>(p_hh, a_heads + (long)l * HH * 2 * FF,
                                             p_s1, p_s2, HH);

        // 3) masked softmax -> att[b,h,n,m]
        k_softmax<<<dim3(NN, HH, BATCH), 128>>>(adj, p_s1, p_s2, p_att, HH);

        // 4) att @ hh, ELU, scattered into multi[b,n,h*F+f]
        k_gemm<<<dim3(1, NN / BM, BATCH * HH), 256>>>(
            p_att, p_hh, p_multi,
            NN, NN,
            (long long)HH * NN * NN, (long long)NN * NN,
            (long long)HH * NN * FF, (long long)NN * FF,
            (long long)NN * HH * FF, (long long)FF,
            HH, HH * FF, 1);

        // 5) out projection: h2 = multi @ W_out[l]   (M = B*N, K = H*F)
        k_gemm<<<dim3(1, (BATCH * NN) / BM, 1), 256>>>(
            p_multi, W_out + (long)l * HH * FF * FF, p_h2,
            BATCH * NN, HH * FF,
            0, 0, 0, 0, 0, 0,
            1, FF, 0);

        // 6) single-head attention vectors + softmax
        k_svec<<<dim3(NN, 1, BATCH), 128>>>(p_h2, a_out + (long)l * 2 * FF,
                                            p_t1, p_t2, 1);
        k_softmax<<<dim3(NN, 1, BATCH), 128>>>(adj, p_t1, p_t2, p_att2, 1);

        // 7) att2 @ h2 -> out[b]
        k_gemm<<<dim3(1, NN / BM, BATCH), 256>>>(
            p_att2, p_h2, p_out,
            NN, NN,
            (long long)NN * NN, 0,
            (long long)NN * FF, 0,
            (long long)NN * FF, 0,
            1, FF, 0);

        // 8) residual + layernorm (+relu except last layer)
        float* dst = (l == LL - 1) ? out : p_h;
        k_lnorm<<<BATCH * NN, 128>>>(p_out, p_h, ln_g + (long)l * FF, ln_b + (long)l * FF,
                                     dst, (l < LL - 1) ? 1 : 0);
    }
}

// round 2
// speedup vs baseline: 1.4480x; 1.4480x over previous
#include <cuda_runtime.h>
#include <cuda_bf16.h>
#include <math.h>

// ---------------- problem constants ----------------
#define BATCH 8
#define NN    512
#define DIN   64
#define HH    8
#define FF    128
#define LL    2
#define NEGV  (-9e15f)

// ---------------- scratch (device globals; no allocs) ----------------
__device__ float g_h    [BATCH * NN * FF];            // current features
__device__ float g_hh   [BATCH * HH * NN * FF];       // per-head projections
__device__ float g_att  [BATCH * HH * NN * NN];       // multi-head attention
__device__ float g_multi[BATCH * NN * HH * FF];       // concat(heads) after ELU
__device__ float g_h2   [BATCH * NN * FF];            // out-proj features
__device__ float g_att2 [BATCH * NN * NN];            // single-head attention
__device__ float g_out  [BATCH * NN * FF];            // single-head output
__device__ float g_s1   [BATCH * HH * NN];
__device__ float g_s2   [BATCH * HH * NN];
__device__ float g_t1   [BATCH * NN];
__device__ float g_t2   [BATCH * NN];

// ---------------- reductions (blockDim.x == 128) ----------------
__device__ __forceinline__ float warpSum(float v) {
#pragma unroll
    for (int o = 16; o > 0; o >>= 1) v += __shfl_xor_sync(0xffffffffu, v, o);
    return v;
}
__device__ __forceinline__ float warpMax(float v) {
#pragma unroll
    for (int o = 16; o > 0; o >>= 1) v = fmaxf(v, __shfl_xor_sync(0xffffffffu, v, o));
    return v;
}
__device__ __forceinline__ float blockSum128(float v) {
    __shared__ float sh[4];
    v = warpSum(v);
    __syncthreads();
    if ((threadIdx.x & 31) == 0) sh[threadIdx.x >> 5] = v;
    __syncthreads();
    return sh[0] + sh[1] + sh[2] + sh[3];
}
__device__ __forceinline__ float blockMax128(float v) {
    __shared__ float sh[4];
    v = warpMax(v);
    __syncthreads();
    if ((threadIdx.x & 31) == 0) sh[threadIdx.x >> 5] = v;
    __syncthreads();
    return fmaxf(fmaxf(sh[0], sh[1]), fmaxf(sh[2], sh[3]));
}

// ---------------- tf32 helpers ----------------
__device__ __forceinline__ unsigned f2tf(float f) {
    unsigned u;
    asm("cvt.rna.tf32.f32 %0, %1;" : "=r"(u) : "f"(f));
    return u;
}
__device__ __forceinline__ void mma_tf32(float c[4], const unsigned a[4], const unsigned b[2]) {
    asm("mma.sync.aligned.m16n8k8.row.col.f32.tf32.tf32.f32 "
        "{%0,%1,%2,%3},{%4,%5,%6,%7},{%8,%9},{%0,%1,%2,%3};"
        : "+f"(c[0]), "+f"(c[1]), "+f"(c[2]), "+f"(c[3])
        : "r"(a[0]), "r"(a[1]), "r"(a[2]), "r"(a[3]), "r"(b[0]), "r"(b[1]));
}

// ---------------- input projection: h = relu(x @ Wp + bp) ----------------
__global__ void k_proj(const float* __restrict__ x, const float* __restrict__ Wp,
                       const float* __restrict__ bp, float* __restrict__ h) {
    __shared__ float xs[DIN];
    const int row = blockIdx.x;
    const int t = threadIdx.x;
    if (t < DIN) xs[t] = x[(long)row * DIN + t];
    __syncthreads();
    float acc = bp[t];
#pragma unroll
    for (int i = 0; i < DIN; i++) acc = fmaf(xs[i], Wp[i * FF + t], acc);
    h[(long)row * FF + t] = fmaxf(acc, 0.f);
}

// ---------------- TF32 tensor-core GEMM ----------------
// C[M,128] = A[M,K] @ B[K,128], row-major, ldb fixed = 128.
// Block tile 128x128xBK16, 8 warps in 4(M) x 2(N), warp tile 32x64 via m16n8k8.
// Batch z decomposed as (b = z/Hb, h = z%Hb). epi: 0 none, 1 ELU.
#define GBM 128
#define GBN 128
#define GBK 16
#define LDA_S 132   // padded smem leading dims
#define LDB_S 132
__global__ __launch_bounds__(256, 2)
void k_gemm(const float* __restrict__ A, const float* __restrict__ B, float* __restrict__ C,
            int M, int K,
            long long sAb, long long sAh,
            long long sBb, long long sBh,
            long long sCb, long long sCh,
            int Hb, int ldc, int epi) {
    const int z = blockIdx.z;
    const int bz = z / Hb, hz = z % Hb;
    A += bz * sAb + hz * sAh;
    B += bz * sBb + hz * sBh;
    C += bz * sCb + hz * sCh;
    const int bm = blockIdx.y * GBM;

    __shared__ unsigned As[GBK][LDA_S];   // [k][m]
    __shared__ unsigned Bs[GBK][LDB_S];   // [k][n]

    const int tid  = threadIdx.x;
    const int lane = tid & 31;
    const int wid  = tid >> 5;
    const int wm = (wid & 3) * 32;    // warp m offset in tile
    const int wn = (wid >> 2) * 64;   // warp n offset in tile
    const int q = lane & 3;           // threadID_in_group
    const int g = lane >> 2;          // groupID

    float acc[2][8][4];
#pragma unroll
    for (int i = 0; i < 2; i++)
#pragma unroll
        for (int j = 0; j < 8; j++)
#pragma unroll
            for (int r = 0; r < 4; r++) acc[i][j][r] = 0.f;

    for (int k0 = 0; k0 < K; k0 += GBK) {
        __syncthreads();   // previous compute done before overwrite
        // stage A tile: 128 x 16 -> As[k][m] (tf32)
        {
#pragma unroll
            for (int p0 = 0; p0 < 2; p0++) {
                const int p = tid + p0 * 256;
                const int row = p >> 2;
                const int c4 = (p & 3) * 4;
                const float4 av = *(const float4*)(A + (long)(bm + row) * K + k0 + c4);
                As[c4 + 0][row] = f2tf(av.x);
                As[c4 + 1][row] = f2tf(av.y);
                As[c4 + 2][row] = f2tf(av.z);
                As[c4 + 3][row] = f2tf(av.w);
            }
        }
        // stage B tile: 16 x 128 -> Bs[k][n] (tf32)
        {
            const int r = tid >> 5;           // warp id = row
            const int c = (tid & 31) * 4;
#pragma unroll
            for (int p0 = 0; p0 < 2; p0++) {
                const int rr = r + p0 * 8;
                const float4 bv = *(const float4*)(B + (long)(k0 + rr) * 128 + c);
                Bs[rr][c + 0] = f2tf(bv.x);
                Bs[rr][c + 1] = f2tf(bv.y);
                Bs[rr][c + 2] = f2tf(bv.z);
                Bs[rr][c + 3] = f2tf(bv.w);
            }
        }
        __syncthreads();

#pragma unroll
        for (int ks = 0; ks < GBK; ks += 8) {
            unsigned bf[8][2];
#pragma unroll
            for (int nt = 0; nt < 8; nt++) {
                const int n0 = wn + nt * 8 + g;
                bf[nt][0] = Bs[ks + q][n0];
                bf[nt][1] = Bs[ks + q + 4][n0];
            }
            unsigned af[2][4];
#pragma unroll
            for (int mt = 0; mt < 2; mt++) {
                const int m0 = wm + mt * 16 + g;
                af[mt][0] = As[ks + q][m0];
                af[mt][1] = As[ks + q][m0 + 8];
                af[mt][2] = As[ks + q + 4][m0];
                af[mt][3] = As[ks + q + 4][m0 + 8];
            }
#pragma unroll
            for (int mt = 0; mt < 2; mt++)
#pragma unroll
                for (int nt = 0; nt < 8; nt++)
                    mma_tf32(acc[mt][nt], af[mt], bf[nt]);
        }
    }

    // epilogue: scatter C fragments
#pragma unroll
    for (int mt = 0; mt < 2; mt++) {
#pragma unroll
        for (int half = 0; half < 2; half++) {
            const int row = bm + wm + mt * 16 + g + half * 8;
            float* crow = C + (long)row * ldc;
#pragma unroll
            for (int nt = 0; nt < 8; nt++) {
                const int col = wn + nt * 8 + 2 * q;
                float v0 = acc[mt][nt][half * 2 + 0];
                float v1 = acc[mt][nt][half * 2 + 1];
                if (epi == 1) {
                    v0 = v0 > 0.f ? v0 : (__expf(v0) - 1.f);
                    v1 = v1 > 0.f ? v1 : (__expf(v1) - 1.f);
                }
                *(float2*)(crow + col) = make_float2(v0, v1);
            }
        }
    }
}

// ---------------- attention score vectors: s1/s2 = hh . a ----------------
__global__ void k_svec(const float* __restrict__ hh, const float* __restrict__ a,
                       float* __restrict__ s1, float* __restrict__ s2, int Hb) {
    const int n = blockIdx.x, h = blockIdx.y, b = blockIdx.z;
    const int t = threadIdx.x;
    const float v = hh[(((long)b * Hb + h) * NN + n) * FF + t];
    const float* av = a + (long)h * (2 * FF);
    float p1 = v * av[t];
    float p2 = v * av[FF + t];
    p1 = blockSum128(p1);
    p2 = blockSum128(p2);
    if (t == 0) {
        const long idx = ((long)b * Hb + h) * NN + n;
        s1[idx] = p1;
        s2[idx] = p2;
    }
}

// ---------------- masked leaky-relu softmax row ----------------
__global__ void k_softmax(const int* __restrict__ adj, const float* __restrict__ s1,
                          const float* __restrict__ s2, float* __restrict__ att, int Hb) {
    const int n = blockIdx.x, h = blockIdx.y, b = blockIdx.z;
    const int t = threadIdx.x;
    const int* adjrow = adj + ((long)b * NN + n) * NN;
    const float* s2row = s2 + ((long)b * Hb + h) * NN;
    const float s1v = s1[((long)b * Hb + h) * NN + n];
    float* arow = att + (((long)b * Hb + h) * NN + n) * NN;

    float v[4];
    float mx = -INFINITY;
#pragma unroll
    for (int j = 0; j < 4; j++) {
        const int m = t + j * 128;
        float e = s1v + s2row[m];
        e = e > 0.f ? e : 0.2f * e;
        v[j] = (adjrow[m] > 0) ? e : NEGV;
        mx = fmaxf(mx, v[j]);
    }
    mx = blockMax128(mx);
    float sum = 0.f;
#pragma unroll
    for (int j = 0; j < 4; j++) {
        v[j] = __expf(v[j] - mx);
        sum += v[j];
    }
    sum = blockSum128(sum);
    const float inv = 1.f / sum;
#pragma unroll
    for (int j = 0; j < 4; j++) arow[t + j * 128] = v[j] * inv;
}

// ---------------- residual + layernorm (+ optional relu) ----------------
__global__ void k_lnorm(const float* __restrict__ o, const float* __restrict__ res,
                        const float* __restrict__ g, const float* __restrict__ bb,
                        float* __restrict__ dst, int do_relu) {
    const int row = blockIdx.x;
    const int t = threadIdx.x;
    const float y = o[(long)row * FF + t] + res[(long)row * FF + t];
    const float mu = blockSum128(y) * (1.f / FF);
    const float d = y - mu;
    const float var = blockSum128(d * d) * (1.f / FF);
    float r = d * rsqrtf(var + 1e-5f) * g[t] + bb[t];
    if (do_relu) r = fmaxf(r, 0.f);
    dst[(long)row * FF + t] = r;
}

// ---------------- host orchestration ----------------
extern "C" void kernel_launch(void* const* d_in, const int* in_sizes, int n_in,
                              void* d_out, int out_size) {
    (void)in_sizes; (void)n_in; (void)out_size;
    const float* x       = (const float*)d_in[0];
    const int*   adj     = (const int*)  d_in[1];
    const float* Wp      = (const float*)d_in[2];
    const float* bp      = (const float*)d_in[3];
    const float* W_heads = (const float*)d_in[4];
    const float* a_heads = (const float*)d_in[5];
    const float* W_out   = (const float*)d_in[6];
    const float* a_out   = (const float*)d_in[7];
    const float* ln_g    = (const float*)d_in[8];
    const float* ln_b    = (const float*)d_in[9];
    float* out = (float*)d_out;

    float *p_h, *p_hh, *p_att, *p_multi, *p_h2, *p_att2, *p_out;
    float *p_s1, *p_s2, *p_t1, *p_t2;
    cudaGetSymbolAddress((void**)&p_h, g_h);
    cudaGetSymbolAddress((void**)&p_hh, g_hh);
    cudaGetSymbolAddress((void**)&p_att, g_att);
    cudaGetSymbolAddress((void**)&p_multi, g_multi);
    cudaGetSymbolAddress((void**)&p_h2, g_h2);
    cudaGetSymbolAddress((void**)&p_att2, g_att2);
    cudaGetSymbolAddress((void**)&p_out, g_out);
    cudaGetSymbolAddress((void**)&p_s1, g_s1);
    cudaGetSymbolAddress((void**)&p_s2, g_s2);
    cudaGetSymbolAddress((void**)&p_t1, g_t1);
    cudaGetSymbolAddress((void**)&p_t2, g_t2);

    k_proj<<<BATCH * NN, 128>>>(x, Wp, bp, p_h);

    for (int l = 0; l < LL; l++) {
        // 1) per-head projection: hh[b,h] = h[b] @ W_heads[l,h]
        k_gemm<<<dim3(1, NN / GBM, BATCH * HH), 256>>>(
            p_h, W_heads + (long)l * HH * FF * FF, p_hh,
            NN, FF,
            (long long)NN * FF, 0,
            0, (long long)FF * FF,
            (long long)HH * NN * FF, (long long)NN * FF,
            HH, FF, 0);

        // 2) attention score vectors
        k_svec<<<dim3(NN, HH, BATCH), 128>>>(p_hh, a_heads + (long)l * HH * 2 * FF,
                                             p_s1, p_s2, HH);

        // 3) masked softmax -> att[b,h,n,m]
        k_softmax<<<dim3(NN, HH, BATCH), 128>>>(adj, p_s1, p_s2, p_att, HH);

        // 4) att @ hh, ELU, scattered into multi[b,n,h*F+f]
        k_gemm<<<dim3(1, NN / GBM, BATCH * HH), 256>>>(
            p_att, p_hh, p_multi,
            NN, NN,
            (long long)HH * NN * NN, (long long)NN * NN,
            (long long)HH * NN * FF, (long long)NN * FF,
            (long long)NN * HH * FF, (long long)FF,
            HH, HH * FF, 1);

        // 5) out projection: h2 = multi @ W_out[l]
        k_gemm<<<dim3(1, (BATCH * NN) / GBM, 1), 256>>>(
            p_multi, W_out + (long)l * HH * FF * FF, p_h2,
            BATCH * NN, HH * FF,
            0, 0, 0, 0, 0, 0,
            1, FF, 0);

        // 6) single-head attention vectors + softmax
        k_svec<<<dim3(NN, 1, BATCH), 128>>>(p_h2, a_out + (long)l * 2 * FF,
                                            p_t1, p_t2, 1);
        k_softmax<<<dim3(NN, 1, BATCH), 128>>>(adj, p_t1, p_t2, p_att2, 1);

        // 7) att2 @ h2 -> out[b]
        k_gemm<<<dim3(1, NN / GBM, BATCH), 256>>>(
            p_att2, p_h2, p_out,
            NN, NN,
            (long long)NN * NN, 0,
            (long long)NN * FF, 0,
            (long long)NN * FF, 0,
            1, FF, 0);

        // 8) residual + layernorm (+relu except last layer)
        float* dst = (l == LL - 1) ? out : p_h;
        k_lnorm<<<BATCH * NN, 128>>>(p_out, p_h, ln_g + (long)l * FF, ln_b + (long)l * FF,
                                     dst, (l < LL - 1) ? 1 : 0);
    }
}

// round 3
// speedup vs baseline: 1.7168x; 1.1856x over previous
#include <cuda_runtime.h>
#include <cuda_bf16.h>
#include <math.h>

// ---------------- problem constants ----------------
#define BATCH 8
#define NN    512
#define DIN   64
#define HH    8
#define FF    128
#define LL    2
#define NEGV  (-9e15f)

// ---------------- scratch (device globals; no allocs) ----------------
__device__ float g_h    [BATCH * NN * FF];
__device__ float g_hh   [BATCH * HH * NN * FF];
__device__ float g_att  [BATCH * HH * NN * NN];
__device__ float g_multi[BATCH * NN * HH * FF];
__device__ float g_h2   [BATCH * NN * FF];
__device__ float g_att2 [BATCH * NN * NN];
__device__ float g_out  [BATCH * NN * FF];
__device__ float g_s1   [BATCH * HH * NN];
__device__ float g_s2   [BATCH * HH * NN];
__device__ float g_t1   [BATCH * NN];
__device__ float g_t2   [BATCH * NN];

// ---------------- warp/block reductions ----------------
__device__ __forceinline__ float warpSum(float v) {
#pragma unroll
    for (int o = 16; o > 0; o >>= 1) v += __shfl_xor_sync(0xffffffffu, v, o);
    return v;
}
__device__ __forceinline__ float warpMax(float v) {
#pragma unroll
    for (int o = 16; o > 0; o >>= 1) v = fmaxf(v, __shfl_xor_sync(0xffffffffu, v, o));
    return v;
}
__device__ __forceinline__ float blockSum128(float v) {
    __shared__ float sh[4];
    v = warpSum(v);
    __syncthreads();
    if ((threadIdx.x & 31) == 0) sh[threadIdx.x >> 5] = v;
    __syncthreads();
    return sh[0] + sh[1] + sh[2] + sh[3];
}
__device__ __forceinline__ float blockMax128(float v) {
    __shared__ float sh[4];
    v = warpMax(v);
    __syncthreads();
    if ((threadIdx.x & 31) == 0) sh[threadIdx.x >> 5] = v;
    __syncthreads();
    return fmaxf(fmaxf(sh[0], sh[1]), fmaxf(sh[2], sh[3]));
}

// ---------------- tf32 helpers ----------------
__device__ __forceinline__ unsigned f2tf(float f) {
    unsigned u;
    asm("cvt.rna.tf32.f32 %0, %1;" : "=r"(u) : "f"(f));
    return u;
}
__device__ __forceinline__ void mma_tf32(float c[4], const unsigned a[4], const unsigned b[2]) {
    asm("mma.sync.aligned.m16n8k8.row.col.f32.tf32.tf32.f32 "
        "{%0,%1,%2,%3},{%4,%5,%6,%7},{%8,%9},{%0,%1,%2,%3};"
        : "+f"(c[0]), "+f"(c[1]), "+f"(c[2]), "+f"(c[3])
        : "r"(a[0]), "r"(a[1]), "r"(a[2]), "r"(a[3]), "r"(b[0]), "r"(b[1]));
}

// ---------------- input projection: h = relu(x @ Wp + bp) ----------------
__global__ void k_proj(const float* __restrict__ x, const float* __restrict__ Wp,
                       const float* __restrict__ bp, float* __restrict__ h) {
    __shared__ float xs[DIN];
    const int row = blockIdx.x;
    const int t = threadIdx.x;
    if (t < DIN) xs[t] = x[(long)row * DIN + t];
    __syncthreads();
    float acc = bp[t];
#pragma unroll
    for (int i = 0; i < DIN; i++) acc = fmaf(xs[i], Wp[i * FF + t], acc);
    h[(long)row * FF + t] = fmaxf(acc, 0.f);
}

// ---------------- pipelined TF32 tensor-core GEMM ----------------
// C[M,128] = A[M,K] @ B[K,128], row-major, ldb fixed = 128.
// Block tile 128x128, K-step 16, double-buffered smem, 8 warps 4(M)x2(N),
// warp tile 32x64 via m16n8k8. Batch z = (b = z/Hb, h = z%Hb).
// epi: 0 none, 1 ELU.
#define GBM 128
#define GBK 16
#define ALD 20    // As row pitch (words): banks (20m+q)%32 conflict-free
#define BLD 136   // Bs row pitch (words): banks (8q+g)%32 conflict-free
__global__ __launch_bounds__(256, 2)
void k_gemm(const float* __restrict__ A, const float* __restrict__ B, float* __restrict__ C,
            int M, int K,
            long long sAb, long long sAh,
            long long sBb, long long sBh,
            long long sCb, long long sCh,
            int Hb, int ldc, int epi) {
    const int z = blockIdx.z;
    const int bz = z / Hb, hz = z % Hb;
    A += bz * sAb + hz * sAh;
    B += bz * sBb + hz * sBh;
    C += bz * sCb + hz * sCh;
    const int bm = blockIdx.y * GBM;

    __shared__ unsigned As[2][GBM][ALD];   // [m][k]
    __shared__ unsigned Bs[2][GBK][BLD];   // [k][n]

    const int tid  = threadIdx.x;
    const int lane = tid & 31;
    const int wid  = tid >> 5;
    const int wm = (wid & 3) * 32;
    const int wn = (wid >> 2) * 64;
    const int q = lane & 3;
    const int g = lane >> 2;

    // staging indices (2 float4 of A, 2 float4 of B per thread)
    const int ar0 = tid >> 1;               // A rows: idx = tid + p*256 -> row = idx>>1? no:
    // A tile 128x16 = 512 float4; thread handles idx = tid, tid+256
    // row = idx>>2 (0..127), kk = (idx&3)*4
    const int br = tid >> 5;                // B rows r, r+8 ; col c
    const int bc = (tid & 31) * 4;
    (void)ar0;

    float acc[2][8][4];
#pragma unroll
    for (int i = 0; i < 2; i++)
#pragma unroll
        for (int j = 0; j < 8; j++)
#pragma unroll
            for (int r = 0; r < 4; r++) acc[i][j][r] = 0.f;

    // ---- prologue: stage tile 0 into buffer 0 ----
    {
#pragma unroll
        for (int p = 0; p < 2; p++) {
            const int idx = tid + p * 256;
            const int row = idx >> 2;
            const int kk = (idx & 3) * 4;
            const float4 av = *(const float4*)(A + (long)(bm + row) * K + kk);
            As[0][row][kk + 0] = f2tf(av.x);
            As[0][row][kk + 1] = f2tf(av.y);
            As[0][row][kk + 2] = f2tf(av.z);
            As[0][row][kk + 3] = f2tf(av.w);
        }
#pragma unroll
        for (int p = 0; p < 2; p++) {
            const int rr = br + p * 8;
            const float4 bv = *(const float4*)(B + (long)rr * 128 + bc);
            Bs[0][rr][bc + 0] = f2tf(bv.x);
            Bs[0][rr][bc + 1] = f2tf(bv.y);
            Bs[0][rr][bc + 2] = f2tf(bv.z);
            Bs[0][rr][bc + 3] = f2tf(bv.w);
        }
    }
    __syncthreads();

    int buf = 0;
    for (int k0 = 0; k0 < K; k0 += GBK) {
        const bool pre = (k0 + GBK) < K;
        float4 pa[2], pb[2];
        if (pre) {
            const int kn = k0 + GBK;
#pragma unroll
            for (int p = 0; p < 2; p++) {
                const int idx = tid + p * 256;
                const int row = idx >> 2;
                const int kk = (idx & 3) * 4;
                pa[p] = *(const float4*)(A + (long)(bm + row) * K + kn + kk);
            }
#pragma unroll
            for (int p = 0; p < 2; p++) {
                const int rr = br + p * 8;
                pb[p] = *(const float4*)(B + (long)(kn + rr) * 128 + bc);
            }
        }

        // ---- compute on current buffer ----
#pragma unroll
        for (int ks = 0; ks < GBK; ks += 8) {
            unsigned bf[8][2];
#pragma unroll
            for (int nt = 0; nt < 8; nt++) {
                const int n0 = wn + nt * 8 + g;
                bf[nt][0] = Bs[buf][ks + q][n0];
                bf[nt][1] = Bs[buf][ks + q + 4][n0];
            }
            unsigned af[2][4];
#pragma unroll
            for (int mt = 0; mt < 2; mt++) {
                const int m0 = wm + mt * 16 + g;
                af[mt][0] = As[buf][m0][ks + q];
                af[mt][1] = As[buf][m0 + 8][ks + q];
                af[mt][2] = As[buf][m0][ks + q + 4];
                af[mt][3] = As[buf][m0 + 8][ks + q + 4];
            }
#pragma unroll
            for (int mt = 0; mt < 2; mt++)
#pragma unroll
                for (int nt = 0; nt < 8; nt++)
                    mma_tf32(acc[mt][nt], af[mt], bf[nt]);
        }

        // ---- stage next tile into other buffer ----
        if (pre) {
            const int nb = buf ^ 1;
#pragma unroll
            for (int p = 0; p < 2; p++) {
                const int idx = tid + p * 256;
                const int row = idx >> 2;
                const int kk = (idx & 3) * 4;
                As[nb][row][kk + 0] = f2tf(pa[p].x);
                As[nb][row][kk + 1] = f2tf(pa[p].y);
                As[nb][row][kk + 2] = f2tf(pa[p].z);
                As[nb][row][kk + 3] = f2tf(pa[p].w);
            }
#pragma unroll
            for (int p = 0; p < 2; p++) {
                const int rr = br + p * 8;
                Bs[nb][rr][bc + 0] = f2tf(pb[p].x);
                Bs[nb][rr][bc + 1] = f2tf(pb[p].y);
                Bs[nb][rr][bc + 2] = f2tf(pb[p].z);
                Bs[nb][rr][bc + 3] = f2tf(pb[p].w);
            }
            __syncthreads();
            buf = nb;
        }
    }

    // ---- epilogue ----
#pragma unroll
    for (int mt = 0; mt < 2; mt++) {
#pragma unroll
        for (int half = 0; half < 2; half++) {
            const int row = bm + wm + mt * 16 + g + half * 8;
            float* crow = C + (long)row * ldc;
#pragma unroll
            for (int nt = 0; nt < 8; nt++) {
                const int col = wn + nt * 8 + 2 * q;
                float v0 = acc[mt][nt][half * 2 + 0];
                float v1 = acc[mt][nt][half * 2 + 1];
                if (epi == 1) {
                    v0 = v0 > 0.f ? v0 : (__expf(v0) - 1.f);
                    v1 = v1 > 0.f ? v1 : (__expf(v1) - 1.f);
                }
                *(float2*)(crow + col) = make_float2(v0, v1);
            }
        }
    }
}

// ---------------- attention score vectors: s1/s2 = hh . a ----------------
__global__ void k_svec(const float* __restrict__ hh, const float* __restrict__ a,
                       float* __restrict__ s1, float* __restrict__ s2, int Hb) {
    const int n = blockIdx.x, h = blockIdx.y, b = blockIdx.z;
    const int t = threadIdx.x;
    const float v = hh[(((long)b * Hb + h) * NN + n) * FF + t];
    const float* av = a + (long)h * (2 * FF);
    float p1 = v * av[t];
    float p2 = v * av[FF + t];
    p1 = blockSum128(p1);
    p2 = blockSum128(p2);
    if (t == 0) {
        const long idx = ((long)b * Hb + h) * NN + n;
        s1[idx] = p1;
        s2[idx] = p2;
    }
}

// ---------------- head-fused masked softmax: all 8 heads per (b,n) ----------------
// grid (NN, BATCH), 256 threads. adj row loaded once.
__global__ __launch_bounds__(256)
void k_softmax8(const int* __restrict__ adj, const float* __restrict__ s1,
                const float* __restrict__ s2, float* __restrict__ att) {
    const int n = blockIdx.x, b = blockIdx.y;
    const int t = threadIdx.x;
    const int lane = t & 31, wid = t >> 5;
    __shared__ float msel[NN];
    __shared__ float red[8];
    const int* adjrow = adj + ((long)b * NN + n) * NN;
#pragma unroll
    for (int j = 0; j < 2; j++) {
        const int m = t + j * 256;
        msel[m] = (adjrow[m] > 0) ? 1.f : 0.f;
    }
    __syncthreads();

#pragma unroll
    for (int h = 0; h < HH; h++) {
        const long base = ((long)b * HH + h) * NN;
        const float s1v = s1[base + n];
        const float* s2row = s2 + base;
        float v[2];
        float mx = -INFINITY;
#pragma unroll
        for (int j = 0; j < 2; j++) {
            const int m = t + j * 256;
            float e = s1v + s2row[m];
            e = e > 0.f ? e : 0.2f * e;
            v[j] = (msel[m] > 0.f) ? e : NEGV;
            mx = fmaxf(mx, v[j]);
        }
        mx = warpMax(mx);
        if (lane == 0) red[wid] = mx;
        __syncthreads();
        mx = fmaxf(fmaxf(fmaxf(red[0], red[1]), fmaxf(red[2], red[3])),
                   fmaxf(fmaxf(red[4], red[5]), fmaxf(red[6], red[7])));
        float sum = 0.f;
#pragma unroll
        for (int j = 0; j < 2; j++) {
            v[j] = __expf(v[j] - mx);
            sum += v[j];
        }
        sum = warpSum(sum);
        __syncthreads();            // red reuse
        if (lane == 0) red[wid] = sum;
        __syncthreads();
        sum = red[0] + red[1] + red[2] + red[3] + red[4] + red[5] + red[6] + red[7];
        const float inv = 1.f / sum;
        float* arow = att + (base + n) * NN;
#pragma unroll
        for (int j = 0; j < 2; j++) arow[t + j * 256] = v[j] * inv;
        __syncthreads();            // red reuse next head
    }
}

// ---------------- single-head masked softmax (as round 2) ----------------
__global__ void k_softmax(const int* __restrict__ adj, const float* __restrict__ s1,
                          const float* __restrict__ s2, float* __restrict__ att, int Hb) {
    const int n = blockIdx.x, h = blockIdx.y, b = blockIdx.z;
    const int t = threadIdx.x;
    const int* adjrow = adj + ((long)b * NN + n) * NN;
    const float* s2row = s2 + ((long)b * Hb + h) * NN;
    const float s1v = s1[((long)b * Hb + h) * NN + n];
    float* arow = att + (((long)b * Hb + h) * NN + n) * NN;

    float v[4];
    float mx = -INFINITY;
#pragma unroll
    for (int j = 0; j < 4; j++) {
        const int m = t + j * 128;
        float e = s1v + s2row[m];
        e = e > 0.f ? e : 0.2f * e;
        v[j] = (adjrow[m] > 0) ? e : NEGV;
        mx = fmaxf(mx, v[j]);
    }
    mx = blockMax128(mx);
    float sum = 0.f;
#pragma unroll
    for (int j = 0; j < 4; j++) {
        v[j] = __expf(v[j] - mx);
        sum += v[j];
    }
    sum = blockSum128(sum);
    const float inv = 1.f / sum;
#pragma unroll
    for (int j = 0; j < 4; j++) arow[t + j * 128] = v[j] * inv;
}

// ---------------- residual + layernorm (+ optional relu) ----------------
__global__ void k_lnorm(const float* __restrict__ o, const float* __restrict__ res,
                        const float* __restrict__ g, const float* __restrict__ bb,
                        float* __restrict__ dst, int do_relu) {
    const int row = blockIdx.x;
    const int t = threadIdx.x;
    const float y = o[(long)row * FF + t] + res[(long)row * FF + t];
    const float mu = blockSum128(y) * (1.f / FF);
    const float d = y - mu;
    const float var = blockSum128(d * d) * (1.f / FF);
    float r = d * rsqrtf(var + 1e-5f) * g[t] + bb[t];
    if (do_relu) r = fmaxf(r, 0.f);
    dst[(long)row * FF + t] = r;
}

// ---------------- host orchestration ----------------
extern "C" void kernel_launch(void* const* d_in, const int* in_sizes, int n_in,
                              void* d_out, int out_size) {
    (void)in_sizes; (void)n_in; (void)out_size;
    const float* x       = (const float*)d_in[0];
    const int*   adj     = (const int*)  d_in[1];
    const float* Wp      = (const float*)d_in[2];
    const float* bp      = (const float*)d_in[3];
    const float* W_heads = (const float*)d_in[4];
    const float* a_heads = (const float*)d_in[5];
    const float* W_out   = (const float*)d_in[6];
    const float* a_out   = (const float*)d_in[7];
    const float* ln_g    = (const float*)d_in[8];
    const float* ln_b    = (const float*)d_in[9];
    float* out = (float*)d_out;

    float *p_h, *p_hh, *p_att, *p_multi, *p_h2, *p_att2, *p_out;
    float *p_s1, *p_s2, *p_t1, *p_t2;
    cudaGetSymbolAddress((void**)&p_h, g_h);
    cudaGetSymbolAddress((void**)&p_hh, g_hh);
    cudaGetSymbolAddress((void**)&p_att, g_att);
    cudaGetSymbolAddress((void**)&p_multi, g_multi);
    cudaGetSymbolAddress((void**)&p_h2, g_h2);
    cudaGetSymbolAddress((void**)&p_att2, g_att2);
    cudaGetSymbolAddress((void**)&p_out, g_out);
    cudaGetSymbolAddress((void**)&p_s1, g_s1);
    cudaGetSymbolAddress((void**)&p_s2, g_s2);
    cudaGetSymbolAddress((void**)&p_t1, g_t1);
    cudaGetSymbolAddress((void**)&p_t2, g_t2);

    k_proj<<<BATCH * NN, 128>>>(x, Wp, bp, p_h);

    for (int l = 0; l < LL; l++) {
        // 1) per-head projection: hh[b,h] = h[b] @ W_heads[l,h]
        k_gemm<<<dim3(1, NN / GBM, BATCH * HH), 256>>>(
            p_h, W_heads + (long)l * HH * FF * FF, p_hh,
            NN, FF,
            (long long)NN * FF, 0,
            0, (long long)FF * FF,
            (long long)HH * NN * FF, (long long)NN * FF,
            HH, FF, 0);

        // 2) attention score vectors
        k_svec<<<dim3(NN, HH, BATCH), 128>>>(p_hh, a_heads + (long)l * HH * 2 * FF,
                                             p_s1, p_s2, HH);

        // 3) head-fused masked softmax -> att[b,h,n,m]
        k_softmax8<<<dim3(NN, BATCH), 256>>>(adj, p_s1, p_s2, p_att);

        // 4) att @ hh, ELU, scattered into multi[b,n,h*F+f]
        k_gemm<<<dim3(1, NN / GBM, BATCH * HH), 256>>>(
            p_att, p_hh, p_multi,
            NN, NN,
            (long long)HH * NN * NN, (long long)NN * NN,
            (long long)HH * NN * FF, (long long)NN * FF,
            (long long)NN * HH * FF, (long long)FF,
            HH, HH * FF, 1);

        // 5) out projection: h2 = multi @ W_out[l]
        k_gemm<<<dim3(1, (BATCH * NN) / GBM, 1), 256>>>(
            p_multi, W_out + (long)l * HH * FF * FF, p_h2,
            BATCH * NN, HH * FF,
            0, 0, 0, 0, 0, 0,
            1, FF, 0);

        // 6) single-head attention vectors + softmax
        k_svec<<<dim3(NN, 1, BATCH), 128>>>(p_h2, a_out + (long)l * 2 * FF,
                                            p_t1, p_t2, 1);
        k_softmax<<<dim3(NN, 1, BATCH), 128>>>(adj, p_t1, p_t2, p_att2, 1);

        // 7) att2 @ h2 -> out[b]
        k_gemm<<<dim3(1, NN / GBM, BATCH), 256>>>(
            p_att2, p_h2, p_out,
            NN, NN,
            (long long)NN * NN, 0,
            (long long)NN * FF, 0,
            (long long)NN * FF, 0,
            1, FF, 0);

        // 8) residual + layernorm (+relu except last layer)
        float* dst = (l == LL - 1) ? out : p_h;
        k_lnorm<<<BATCH * NN, 128>>>(p_out, p_h, ln_g + (long)l * FF, ln_b + (long)l * FF,
                                     dst, (l < LL - 1) ? 1 : 0);
    }
}

// round 5
// speedup vs baseline: 2.0669x; 1.2039x over previous
#include <cuda_runtime.h>
#include <cuda_bf16.h>
#include <math.h>

// ---------------- problem constants ----------------
#define BATCH 8
#define NN    512
#define DIN   64
#define HH    8
#define FF    128
#define LL    2
#define NEGV  (-9e15f)

// ---------------- scratch (device globals; no allocs) ----------------
__device__ float g_h    [BATCH * NN * FF];
__device__ float g_hh   [BATCH * HH * NN * FF];
__device__ float g_att  [BATCH * HH * NN * NN];
__device__ float g_multi[BATCH * NN * HH * FF];
__device__ float g_h2   [BATCH * NN * FF];
__device__ float g_att2 [BATCH * NN * NN];
__device__ float g_out  [BATCH * NN * FF];
__device__ float g_part [4 * BATCH * NN * FF];        // split-K partials
__device__ float g_s1   [BATCH * HH * NN];
__device__ float g_s2   [BATCH * HH * NN];
__device__ float g_t1   [BATCH * NN];
__device__ float g_t2   [BATCH * NN];

// ---------------- reductions ----------------
__device__ __forceinline__ float warpSum(float v) {
#pragma unroll
    for (int o = 16; o > 0; o >>= 1) v += __shfl_xor_sync(0xffffffffu, v, o);
    return v;
}
__device__ __forceinline__ float warpMax(float v) {
#pragma unroll
    for (int o = 16; o > 0; o >>= 1) v = fmaxf(v, __shfl_xor_sync(0xffffffffu, v, o));
    return v;
}
__device__ __forceinline__ float blockSum128(float v) {
    __shared__ float sh[4];
    v = warpSum(v);
    __syncthreads();
    if ((threadIdx.x & 31) == 0) sh[threadIdx.x >> 5] = v;
    __syncthreads();
    return sh[0] + sh[1] + sh[2] + sh[3];
}
__device__ __forceinline__ float blockMax128(float v) {
    __shared__ float sh[4];
    v = warpMax(v);
    __syncthreads();
    if ((threadIdx.x & 31) == 0) sh[threadIdx.x >> 5] = v;
    __syncthreads();
    return fmaxf(fmaxf(sh[0], sh[1]), fmaxf(sh[2], sh[3]));
}

// ---------------- tf32 helpers ----------------
// RNA-to-tf32 rounding via integer add: for finite non-NaN x,
// (bits(x) + 0x1000) truncated to the top 19 bits == cvt.rna.tf32(x).
__device__ __forceinline__ unsigned rtf(float f) {
    return __float_as_uint(f) + 0x1000u;
}
__device__ __forceinline__ void mma_tf32(float c[4], const unsigned a[4], const unsigned b0, const unsigned b1) {
    asm("mma.sync.aligned.m16n8k8.row.col.f32.tf32.tf32.f32 "
        "{%0,%1,%2,%3},{%4,%5,%6,%7},{%8,%9},{%0,%1,%2,%3};"
        : "+f"(c[0]), "+f"(c[1]), "+f"(c[2]), "+f"(c[3])
        : "r"(a[0]), "r"(a[1]), "r"(a[2]), "r"(a[3]), "r"(b0), "r"(b1));
}

// ---------------- input projection ----------------
__global__ void k_proj(const float* __restrict__ x, const float* __restrict__ Wp,
                       const float* __restrict__ bp, float* __restrict__ h) {
    __shared__ float xs[DIN];
    const int row = blockIdx.x;
    const int t = threadIdx.x;
    if (t < DIN) xs[t] = x[(long)row * DIN + t];
    __syncthreads();
    float acc = bp[t];
#pragma unroll
    for (int i = 0; i < DIN; i++) acc = fmaf(xs[i], Wp[i * FF + t], acc);
    h[(long)row * FF + t] = fmaxf(acc, 0.f);
}

// ---------------- pipelined TF32 tensor-core GEMM (vector fragment loads) ----------------
// C[M,128] = A[M,Kc*S] @ B[Kc*S,128], row-major, ldb = 128.
// Block tile 128x128, K-step 16, double-buffered smem, 8 warps 4(M)x2(N).
// blockIdx.z = (z2 * S + s): s = K split index, z2 = (b*Hb + h) batch index.
// A smem: [m][perm_k], perm(k) = ((k&3)<<1)|((k>>2)&1)|(k&8)  -> (k,k+4) adjacent (LDS.64)
// B smem: [k][perm_n], s(n) = ((n>>3)&7) + ((n&7)<<3) + (n&64) -> 8 nt contiguous (LDS.128)
#define GBM 128
#define GBK 16
#define ALD 24
#define BLD 136
__global__ __launch_bounds__(256, 2)
void k_gemm(const float* __restrict__ A, const float* __restrict__ B,
            float* __restrict__ C, float* __restrict__ Cpart,
            int M, int Kc,
            long long sAb, long long sAh,
            long long sBb, long long sBh,
            long long sCb, long long sCh,
            int Hb, int ldc, int epi, int S, long long TOT) {
    const int zz = blockIdx.z;
    const int s = zz % S;
    const int z2 = zz / S;
    const int bz = z2 / Hb, hz = z2 % Hb;
    A += bz * sAb + hz * sAh + (long long)s * Kc;
    B += bz * sBb + hz * sBh + (long long)s * Kc * 128;
    C += bz * sCb + hz * sCh;
    const int bm = blockIdx.y * GBM;

    __shared__ unsigned As[2][GBM][ALD];   // [m][perm_k]
    __shared__ unsigned Bs[2][GBK][BLD];   // [k][perm_n]

    const int tid  = threadIdx.x;
    const int lane = tid & 31;
    const int wid  = tid >> 5;
    const int wm = (wid & 3) * 32;
    const int wn = (wid >> 2) * 64;
    const int q = lane & 3;
    const int g = lane >> 2;

    // staging coords
    const int arow0 = tid >> 2;
    const int ac = tid & 3;
    const int aw0 = (ac & 1) + 8 * (ac >> 1);
    const int br = tid >> 5;
    const int bc = lane * 4;

    float acc[2][8][4];
#pragma unroll
    for (int i = 0; i < 2; i++)
#pragma unroll
        for (int j = 0; j < 8; j++)
#pragma unroll
            for (int r = 0; r < 4; r++) acc[i][j][r] = 0.f;

    // ---- prologue: stage tile 0 ----
#pragma unroll
    for (int p = 0; p < 2; p++) {
        const int row = arow0 + p * 64;
        const float4 av = *(const float4*)(A + (long)(bm + row) * (Kc * S) + ac * 4);
        As[0][row][aw0 + 0] = rtf(av.x);
        As[0][row][aw0 + 2] = rtf(av.y);
        As[0][row][aw0 + 4] = rtf(av.z);
        As[0][row][aw0 + 6] = rtf(av.w);
    }
#pragma unroll
    for (int p = 0; p < 2; p++) {
        const int rr = br + p * 8;
        const float4 bv = *(const float4*)(B + (long)rr * 128 + bc);
#pragma unroll
        for (int j = 0; j < 4; j++) {
            const int n = bc + j;
            const int sn = ((n >> 3) & 7) + ((n & 7) << 3) + (n & 64);
            Bs[0][rr][sn] = rtf(j == 0 ? bv.x : j == 1 ? bv.y : j == 2 ? bv.z : bv.w);
        }
    }
    __syncthreads();

    const long long Kfull = (long long)Kc * S;
    int buf = 0;
    for (int k0 = 0; k0 < Kc; k0 += GBK) {
        const bool pre = (k0 + GBK) < Kc;
        float4 pa[2], pb[2];
        if (pre) {
            const int kn = k0 + GBK;
#pragma unroll
            for (int p = 0; p < 2; p++) {
                const int row = arow0 + p * 64;
                pa[p] = *(const float4*)(A + (long)(bm + row) * Kfull + kn + ac * 4);
            }
#pragma unroll
            for (int p = 0; p < 2; p++) {
                const int rr = br + p * 8;
                pb[p] = *(const float4*)(B + (long)(kn + rr) * 128 + bc);
            }
        }

        // ---- compute on current buffer ----
#pragma unroll
        for (int ks = 0; ks < GBK; ks += 8) {
            const unsigned* r0 = &Bs[buf][ks + q][0];
            const unsigned* r1 = &Bs[buf][ks + q + 4][0];
            const uint4 b0a = *(const uint4*)(r0 + wn + 8 * g);
            const uint4 b0b = *(const uint4*)(r0 + wn + 8 * g + 4);
            const uint4 b1a = *(const uint4*)(r1 + wn + 8 * g);
            const uint4 b1b = *(const uint4*)(r1 + wn + 8 * g + 4);
            const unsigned bu0[8] = {b0a.x, b0a.y, b0a.z, b0a.w, b0b.x, b0b.y, b0b.z, b0b.w};
            const unsigned bu1[8] = {b1a.x, b1a.y, b1a.z, b1a.w, b1b.x, b1b.y, b1b.z, b1b.w};
            unsigned af[2][4];
#pragma unroll
            for (int mt = 0; mt < 2; mt++) {
                const int m0 = wm + mt * 16 + g;
                const uint2 a0 = *(const uint2*)&As[buf][m0][ks + 2 * q];
                const uint2 a1 = *(const uint2*)&As[buf][m0 + 8][ks + 2 * q];
                af[mt][0] = a0.x; af[mt][1] = a1.x; af[mt][2] = a0.y; af[mt][3] = a1.y;
            }
#pragma unroll
            for (int mt = 0; mt < 2; mt++)
#pragma unroll
                for (int nt = 0; nt < 8; nt++)
                    mma_tf32(acc[mt][nt], af[mt], bu0[nt], bu1[nt]);
        }

        // ---- stage next tile ----
        if (pre) {
            const int nb = buf ^ 1;
#pragma unroll
            for (int p = 0; p < 2; p++) {
                const int row = arow0 + p * 64;
                As[nb][row][aw0 + 0] = rtf(pa[p].x);
                As[nb][row][aw0 + 2] = rtf(pa[p].y);
                As[nb][row][aw0 + 4] = rtf(pa[p].z);
                As[nb][row][aw0 + 6] = rtf(pa[p].w);
            }
#pragma unroll
            for (int p = 0; p < 2; p++) {
                const int rr = br + p * 8;
#pragma unroll
                for (int j = 0; j < 4; j++) {
                    const int n = bc + j;
                    const int sn = ((n >> 3) & 7) + ((n & 7) << 3) + (n & 64);
                    Bs[nb][rr][sn] = rtf(j == 0 ? pb[p].x : j == 1 ? pb[p].y : j == 2 ? pb[p].z : pb[p].w);
                }
            }
            __syncthreads();
            buf = nb;
        }
    }

    // ---- epilogue ----
#pragma unroll
    for (int mt = 0; mt < 2; mt++) {
#pragma unroll
        for (int half = 0; half < 2; half++) {
            const int row = wm + mt * 16 + g + half * 8;
            if (S == 1) {
                float* crow = C + (long)(bm + row) * ldc;
#pragma unroll
                for (int nt = 0; nt < 8; nt++) {
                    const int col = wn + nt * 8 + 2 * q;
                    float v0 = acc[mt][nt][half * 2 + 0];
                    float v1 = acc[mt][nt][half * 2 + 1];
                    if (epi == 1) {
                        v0 = v0 > 0.f ? v0 : (__expf(v0) - 1.f);
                        v1 = v1 > 0.f ? v1 : (__expf(v1) - 1.f);
                    }
                    *(float2*)(crow + col) = make_float2(v0, v1);
                }
            } else {
                float* prow = Cpart + (long long)s * TOT + ((long long)z2 * M + bm + row) * 128;
#pragma unroll
                for (int nt = 0; nt < 8; nt++) {
                    const int col = wn + nt * 8 + 2 * q;
                    *(float2*)(prow + col) = make_float2(acc[mt][nt][half * 2 + 0],
                                                         acc[mt][nt][half * 2 + 1]);
                }
            }
        }
    }
}

// ---------------- split-K reduction ----------------
__global__ void k_reduce4(const float* __restrict__ part, float* __restrict__ out, long long TOT) {
    const long long i = ((long long)blockIdx.x * 256 + threadIdx.x) * 4;
    float4 a = *(const float4*)(part + i);
    const float4 b = *(const float4*)(part + TOT + i);
    const float4 c = *(const float4*)(part + 2 * TOT + i);
    const float4 d = *(const float4*)(part + 3 * TOT + i);
    a.x += b.x + c.x + d.x;
    a.y += b.y + c.y + d.y;
    a.z += b.z + c.z + d.z;
    a.w += b.w + c.w + d.w;
    *(float4*)(out + i) = a;
}

// ---------------- attention score vectors ----------------
__global__ void k_svec(const float* __restrict__ hh, const float* __restrict__ a,
                       float* __restrict__ s1, float* __restrict__ s2, int Hb) {
    const int n = blockIdx.x, h = blockIdx.y, b = blockIdx.z;
    const int t = threadIdx.x;
    const float v = hh[(((long)b * Hb + h) * NN + n) * FF + t];
    const float* av = a + (long)h * (2 * FF);
    float p1 = v * av[t];
    float p2 = v * av[FF + t];
    p1 = blockSum128(p1);
    p2 = blockSum128(p2);
    if (t == 0) {
        const long idx = ((long)b * Hb + h) * NN + n;
        s1[idx] = p1;
        s2[idx] = p2;
    }
}

// ---------------- masked leaky-relu softmax row ----------------
__global__ void k_softmax(const int* __restrict__ adj, const float* __restrict__ s1,
                          const float* __restrict__ s2, float* __restrict__ att, int Hb) {
    const int n = blockIdx.x, h = blockIdx.y, b = blockIdx.z;
    const int t = threadIdx.x;
    const int* adjrow = adj + ((long)b * NN + n) * NN;
    const float* s2row = s2 + ((long)b * Hb + h) * NN;
    const float s1v = s1[((long)b * Hb + h) * NN + n];
    float* arow = att + (((long)b * Hb + h) * NN + n) * NN;

    float v[4];
    float mx = -INFINITY;
#pragma unroll
    for (int j = 0; j < 4; j++) {
        const int m = t + j * 128;
        float e = s1v + s2row[m];
        e = e > 0.f ? e : 0.2f * e;
        v[j] = (adjrow[m] > 0) ? e : NEGV;
        mx = fmaxf(mx, v[j]);
    }
    mx = blockMax128(mx);
    float sum = 0.f;
#pragma unroll
    for (int j = 0; j < 4; j++) {
        v[j] = __expf(v[j] - mx);
        sum += v[j];
    }
    sum = blockSum128(sum);
    const float inv = 1.f / sum;
#pragma unroll
    for (int j = 0; j < 4; j++) arow[t + j * 128] = v[j] * inv;
}

// ---------------- residual + layernorm (+ optional relu) ----------------
__global__ void k_lnorm(const float* __restrict__ o, const float* __restrict__ res,
                        const float* __restrict__ g, const float* __restrict__ bb,
                        float* __restrict__ dst, int do_relu) {
    const int row = blockIdx.x;
    const int t = threadIdx.x;
    const float y = o[(long)row * FF + t] + res[(long)row * FF + t];
    const float mu = blockSum128(y) * (1.f / FF);
    const float d = y - mu;
    const float var = blockSum128(d * d) * (1.f / FF);
    float r = d * rsqrtf(var + 1e-5f) * g[t] + bb[t];
    if (do_relu) r = fmaxf(r, 0.f);
    dst[(long)row * FF + t] = r;
}

// ---------------- host orchestration ----------------
extern "C" void kernel_launch(void* const* d_in, const int* in_sizes, int n_in,
                              void* d_out, int out_size) {
    (void)in_sizes; (void)n_in; (void)out_size;
    const float* x       = (const float*)d_in[0];
    const int*   adj     = (const int*)  d_in[1];
    const float* Wp      = (const float*)d_in[2];
    const float* bp      = (const float*)d_in[3];
    const float* W_heads = (const float*)d_in[4];
    const float* a_heads = (const float*)d_in[5];
    const float* W_out   = (const float*)d_in[6];
    const float* a_out   = (const float*)d_in[7];
    const float* ln_g    = (const float*)d_in[8];
    const float* ln_b    = (const float*)d_in[9];
    float* out = (float*)d_out;

    float *p_h, *p_hh, *p_att, *p_multi, *p_h2, *p_att2, *p_out, *p_part;
    float *p_s1, *p_s2, *p_t1, *p_t2;
    cudaGetSymbolAddress((void**)&p_h, g_h);
    cudaGetSymbolAddress((void**)&p_hh, g_hh);
    cudaGetSymbolAddress((void**)&p_att, g_att);
    cudaGetSymbolAddress((void**)&p_multi, g_multi);
    cudaGetSymbolAddress((void**)&p_h2, g_h2);
    cudaGetSymbolAddress((void**)&p_att2, g_att2);
    cudaGetSymbolAddress((void**)&p_out, g_out);
    cudaGetSymbolAddress((void**)&p_part, g_part);
    cudaGetSymbolAddress((void**)&p_s1, g_s1);
    cudaGetSymbolAddress((void**)&p_s2, g_s2);
    cudaGetSymbolAddress((void**)&p_t1, g_t1);
    cudaGetSymbolAddress((void**)&p_t2, g_t2);

    const long long TOT = (long long)BATCH * NN * FF;   // 524288

    k_proj<<<BATCH * NN, 128>>>(x, Wp, bp, p_h);

    for (int l = 0; l < LL; l++) {
        // 1) per-head projection: hh[b,h] = h[b] @ W_heads[l,h]
        k_gemm<<<dim3(1, NN / GBM, BATCH * HH), 256>>>(
            p_h, W_heads + (long)l * HH * FF * FF, p_hh, p_part,
            NN, FF,
            (long long)NN * FF, 0,
            0, (long long)FF * FF,
            (long long)HH * NN * FF, (long long)NN * FF,
            HH, FF, 0, 1, 0);

        // 2) attention score vectors
        k_svec<<<dim3(NN, HH, BATCH), 128>>>(p_hh, a_heads + (long)l * HH * 2 * FF,
                                             p_s1, p_s2, HH);

        // 3) masked softmax -> att[b,h,n,m]
        k_softmax<<<dim3(NN, HH, BATCH), 128>>>(adj, p_s1, p_s2, p_att, HH);

        // 4) att @ hh, ELU, scattered into multi[b,n,h*F+f]
        k_gemm<<<dim3(1, NN / GBM, BATCH * HH), 256>>>(
            p_att, p_hh, p_multi, p_part,
            NN, NN,
            (long long)HH * NN * NN, (long long)NN * NN,
            (long long)HH * NN * FF, (long long)NN * FF,
            (long long)NN * HH * FF, (long long)FF,
            HH, HH * FF, 1, 1, 0);

        // 5) out projection: h2 = multi @ W_out[l], split-K S=4
        k_gemm<<<dim3(1, (BATCH * NN) / GBM, 4), 256>>>(
            p_multi, W_out + (long)l * HH * FF * FF, p_h2, p_part,
            BATCH * NN, (HH * FF) / 4,
            0, 0, 0, 0, 0, 0,
            1, FF, 0, 4, TOT);
        k_reduce4<<<(int)(TOT / 4 / 256), 256>>>(p_part, p_h2, TOT);

        // 6) single-head attention vectors + softmax
        k_svec<<<dim3(NN, 1, BATCH), 128>>>(p_h2, a_out + (long)l * 2 * FF,
                                            p_t1, p_t2, 1);
        k_softmax<<<dim3(NN, 1, BATCH), 128>>>(adj, p_t1, p_t2, p_att2, 1);

        // 7) att2 @ h2 -> out[b], split-K S=4
        k_gemm<<<dim3(1, NN / GBM, BATCH * 4), 256>>>(
            p_att2, p_h2, p_out, p_part,
            NN, NN / 4,
            (long long)NN * NN, 0,
            (long long)NN * FF, 0,
            (long long)NN * FF, 0,
            1, FF, 0, 4, TOT);
        k_reduce4<<<(int)(TOT / 4 / 256), 256>>>(p_part, p_out, TOT);

        // 8) residual + layernorm (+relu except last layer)
        float* dst = (l == LL - 1) ? out : p_h;
        k_lnorm<<<BATCH * NN, 128>>>(p_out, p_h, ln_g + (long)l * FF, ln_b + (long)l * FF,
                                     dst, (l < LL - 1) ? 1 : 0);
    }
}

// round 7
// speedup vs baseline: 2.0725x; 1.0027x over previous
#include <cuda_runtime.h>
#include <cuda_bf16.h>
#include <math.h>

// ---------------- problem constants ----------------
#define BATCH 8
#define NN    512
#define DIN   64
#define HH    8
#define FF    128
#define LL    2
#define NEGV  (-9e15f)

// ---------------- scratch (device globals; no allocs) ----------------
__device__ float g_h    [BATCH * NN * FF];
__device__ float g_hh   [BATCH * HH * NN * FF];
__device__ float g_att  [BATCH * HH * NN * NN];
__device__ float g_multi[BATCH * NN * HH * FF];
__device__ float g_h2   [BATCH * NN * FF];
__device__ float g_att2 [BATCH * NN * NN];
__device__ float g_part [4 * BATCH * NN * FF];        // split-K partials
__device__ float g_s1   [BATCH * HH * NN];
__device__ float g_s2   [BATCH * HH * NN];
__device__ float g_t1   [BATCH * NN];
__device__ float g_t2   [BATCH * NN];

// ---------------- reductions ----------------
__device__ __forceinline__ float warpSum(float v) {
#pragma unroll
    for (int o = 16; o > 0; o >>= 1) v += __shfl_xor_sync(0xffffffffu, v, o);
    return v;
}
__device__ __forceinline__ float warpMax(float v) {
#pragma unroll
    for (int o = 16; o > 0; o >>= 1) v = fmaxf(v, __shfl_xor_sync(0xffffffffu, v, o));
    return v;
}
__device__ __forceinline__ float blockSum128(float v) {
    __shared__ float sh[4];
    v = warpSum(v);
    __syncthreads();
    if ((threadIdx.x & 31) == 0) sh[threadIdx.x >> 5] = v;
    __syncthreads();
    return sh[0] + sh[1] + sh[2] + sh[3];
}
__device__ __forceinline__ float blockMax128(float v) {
    __shared__ float sh[4];
    v = warpMax(v);
    __syncthreads();
    if ((threadIdx.x & 31) == 0) sh[threadIdx.x >> 5] = v;
    __syncthreads();
    return fmaxf(fmaxf(sh[0], sh[1]), fmaxf(sh[2], sh[3]));
}

// ---------------- tf32 RNA rounding (bit trick == cvt.rna.tf32) ----------------
__device__ __forceinline__ unsigned rtf(float f) {
    return __float_as_uint(f) + 0x1000u;
}
__device__ __forceinline__ void mma_tf32(float c[4], const unsigned a[4], const unsigned b0, const unsigned b1) {
    asm("mma.sync.aligned.m16n8k8.row.col.f32.tf32.tf32.f32 "
        "{%0,%1,%2,%3},{%4,%5,%6,%7},{%8,%9},{%0,%1,%2,%3};"
        : "+f"(c[0]), "+f"(c[1]), "+f"(c[2]), "+f"(c[3])
        : "r"(a[0]), "r"(a[1]), "r"(a[2]), "r"(a[3]), "r"(b0), "r"(b1));
}

// ---------------- input projection ----------------
__global__ void k_proj(const float* __restrict__ x, const float* __restrict__ Wp,
                       const float* __restrict__ bp, float* __restrict__ h) {
    __shared__ float xs[DIN];
    const int row = blockIdx.x;
    const int t = threadIdx.x;
    if (t < DIN) xs[t] = x[(long)row * DIN + t];
    __syncthreads();
    float acc = bp[t];
#pragma unroll
    for (int i = 0; i < DIN; i++) acc = fmaf(xs[i], Wp[i * FF + t], acc);
    h[(long)row * FF + t] = fmaxf(acc, 0.f);
}

// ---------------- pipelined TF32 tensor-core GEMM (templated K/S/epi) ----------------
// C[M,128] = A[M,KC*S] @ B[KC*S,128], row-major, ldb = 128.
// Block tile 128x128, K-step 16, double-buffered smem, 8 warps 4(M)x2(N).
// blockIdx.z = (z2 * S + s). EPI: 0 none, 1 ELU.
#define GBM 128
#define GBK 16
#define ALD 24
#define BLD 136
template <int KC, int S, int EPI>
__global__ __launch_bounds__(256, 2)
void k_gemm_t(const float* __restrict__ A, const float* __restrict__ B,
              float* __restrict__ C, float* __restrict__ Cpart,
              int M,
              long long sAb, long long sAh,
              long long sBb, long long sBh,
              long long sCb, long long sCh,
              int Hb, int ldc, long long TOT) {
    const int zz = blockIdx.z;
    const int s = zz % S;
    const int z2 = zz / S;
    const int bz = z2 / Hb, hz = z2 % Hb;
    A += bz * sAb + hz * sAh + (long long)s * KC;
    B += bz * sBb + hz * sBh + (long long)s * KC * 128;
    C += bz * sCb + hz * sCh;
    const int bm = blockIdx.y * GBM;
    constexpr long long Kfull = (long long)KC * S;

    __shared__ unsigned As[2][GBM][ALD];   // [m][perm_k]
    __shared__ unsigned Bs[2][GBK][BLD];   // [k][perm_n]

    const int tid  = threadIdx.x;
    const int lane = tid & 31;
    const int wid  = tid >> 5;
    const int wm = (wid & 3) * 32;
    const int wn = (wid >> 2) * 64;
    const int q = lane & 3;
    const int g = lane >> 2;

    const int arow0 = tid >> 2;
    const int ac = tid & 3;
    const int aw0 = (ac & 1) + 8 * (ac >> 1);
    const int br = tid >> 5;
    const int bc = lane * 4;

    float acc[2][8][4];
#pragma unroll
    for (int i = 0; i < 2; i++)
#pragma unroll
        for (int j = 0; j < 8; j++)
#pragma unroll
            for (int r = 0; r < 4; r++) acc[i][j][r] = 0.f;

    // ---- prologue: stage tile 0 ----
#pragma unroll
    for (int p = 0; p < 2; p++) {
        const int row = arow0 + p * 64;
        const float4 av = *(const float4*)(A + (long long)(bm + row) * Kfull + ac * 4);
        As[0][row][aw0 + 0] = rtf(av.x);
        As[0][row][aw0 + 2] = rtf(av.y);
        As[0][row][aw0 + 4] = rtf(av.z);
        As[0][row][aw0 + 6] = rtf(av.w);
    }
#pragma unroll
    for (int p = 0; p < 2; p++) {
        const int rr = br + p * 8;
        const float4 bv = *(const float4*)(B + (long long)rr * 128 + bc);
#pragma unroll
        for (int j = 0; j < 4; j++) {
            const int n = bc + j;
            const int sn = ((n >> 3) & 7) + ((n & 7) << 3) + (n & 64);
            Bs[0][rr][sn] = rtf(j == 0 ? bv.x : j == 1 ? bv.y : j == 2 ? bv.z : bv.w);
        }
    }
    __syncthreads();

    int buf = 0;
#pragma unroll 2
    for (int k0 = 0; k0 < KC; k0 += GBK) {
        const bool pre = (k0 + GBK) < KC;
        float4 pa[2], pb[2];
        if (pre) {
            const int kn = k0 + GBK;
#pragma unroll
            for (int p = 0; p < 2; p++) {
                const int row = arow0 + p * 64;
                pa[p] = *(const float4*)(A + (long long)(bm + row) * Kfull + kn + ac * 4);
            }
#pragma unroll
            for (int p = 0; p < 2; p++) {
                const int rr = br + p * 8;
                pb[p] = *(const float4*)(B + (long long)(kn + rr) * 128 + bc);
            }
        }

        // ---- compute on current buffer ----
#pragma unroll
        for (int ks = 0; ks < GBK; ks += 8) {
            const unsigned* r0 = &Bs[buf][ks + q][0];
            const unsigned* r1 = &Bs[buf][ks + q + 4][0];
            const uint4 b0a = *(const uint4*)(r0 + wn + 8 * g);
            const uint4 b0b = *(const uint4*)(r0 + wn + 8 * g + 4);
            const uint4 b1a = *(const uint4*)(r1 + wn + 8 * g);
            const uint4 b1b = *(const uint4*)(r1 + wn + 8 * g + 4);
            const unsigned bu0[8] = {b0a.x, b0a.y, b0a.z, b0a.w, b0b.x, b0b.y, b0b.z, b0b.w};
            const unsigned bu1[8] = {b1a.x, b1a.y, b1a.z, b1a.w, b1b.x, b1b.y, b1b.z, b1b.w};
            unsigned af[2][4];
#pragma unroll
            for (int mt = 0; mt < 2; mt++) {
                const int m0 = wm + mt * 16 + g;
                const uint2 a0 = *(const uint2*)&As[buf][m0][ks + 2 * q];
                const uint2 a1 = *(const uint2*)&As[buf][m0 + 8][ks + 2 * q];
                af[mt][0] = a0.x; af[mt][1] = a1.x; af[mt][2] = a0.y; af[mt][3] = a1.y;
            }
#pragma unroll
            for (int mt = 0; mt < 2; mt++)
#pragma unroll
                for (int nt = 0; nt < 8; nt++)
                    mma_tf32(acc[mt][nt], af[mt], bu0[nt], bu1[nt]);
        }

        // ---- stage next tile ----
        if (pre) {
            const int nb = buf ^ 1;
#pragma unroll
            for (int p = 0; p < 2; p++) {
                const int row = arow0 + p * 64;
                As[nb][row][aw0 + 0] = rtf(pa[p].x);
                As[nb][row][aw0 + 2] = rtf(pa[p].y);
                As[nb][row][aw0 + 4] = rtf(pa[p].z);
                As[nb][row][aw0 + 6] = rtf(pa[p].w);
            }
#pragma unroll
            for (int p = 0; p < 2; p++) {
                const int rr = br + p * 8;
#pragma unroll
                for (int j = 0; j < 4; j++) {
                    const int n = bc + j;
                    const int sn = ((n >> 3) & 7) + ((n & 7) << 3) + (n & 64);
                    Bs[nb][rr][sn] = rtf(j == 0 ? pb[p].x : j == 1 ? pb[p].y : j == 2 ? pb[p].z : pb[p].w);
                }
            }
            __syncthreads();
            buf = nb;
        }
    }

    // ---- epilogue ----
#pragma unroll
    for (int mt = 0; mt < 2; mt++) {
#pragma unroll
        for (int half = 0; half < 2; half++) {
            const int row = wm + mt * 16 + g + half * 8;
            if (S == 1) {
                float* crow = C + (long long)(bm + row) * ldc;
#pragma unroll
                for (int nt = 0; nt < 8; nt++) {
                    const int col = wn + nt * 8 + 2 * q;
                    float v0 = acc[mt][nt][half * 2 + 0];
                    float v1 = acc[mt][nt][half * 2 + 1];
                    if (EPI == 1) {
                        v0 = v0 > 0.f ? v0 : (__expf(v0) - 1.f);
                        v1 = v1 > 0.f ? v1 : (__expf(v1) - 1.f);
                    }
                    *(float2*)(crow + col) = make_float2(v0, v1);
                }
            } else {
                float* prow = Cpart + (long long)s * TOT + ((long long)z2 * M + bm + row) * 128;
#pragma unroll
                for (int nt = 0; nt < 8; nt++) {
                    const int col = wn + nt * 8 + 2 * q;
                    *(float2*)(prow + col) = make_float2(acc[mt][nt][half * 2 + 0],
                                                         acc[mt][nt][half * 2 + 1]);
                }
            }
        }
    }
}

// ---------------- fused split-K reduce + svec (h2 = sum partials; t1/t2 = h2 . a) ----------------
__global__ void k_red_svec(const float* __restrict__ part, float* __restrict__ h2,
                           const float* __restrict__ a, float* __restrict__ t1,
                           float* __restrict__ t2, long long TOT) {
    const int row = blockIdx.x;             // b*NN + n
    const int t = threadIdx.x;              // 0..127 = f
    const long long i = (long long)row * FF + t;
    float v = part[i] + (part[TOT + i] + part[2 * TOT + i] + part[3 * TOT + i]);
    h2[i] = v;
    float p1 = v * a[t];
    float p2 = v * a[FF + t];
    p1 = blockSum128(p1);
    p2 = blockSum128(p2);
    if (t == 0) {
        t1[row] = p1;
        t2[row] = p2;
    }
}

// ---------------- fused split-K reduce + residual + layernorm (+relu) ----------------
__global__ void k_red_lnorm(const float* __restrict__ part, const float* __restrict__ res,
                            const float* __restrict__ g, const float* __restrict__ bb,
                            float* __restrict__ dst, int do_relu, long long TOT) {
    const int row = blockIdx.x;
    const int t = threadIdx.x;
    const long long i = (long long)row * FF + t;
    const float o = part[i] + (part[TOT + i] + part[2 * TOT + i] + part[3 * TOT + i]);
    const float y = o + res[i];
    const float mu = blockSum128(y) * (1.f / FF);
    const float d = y - mu;
    const float var = blockSum128(d * d) * (1.f / FF);
    float r = d * rsqrtf(var + 1e-5f) * g[t] + bb[t];
    if (do_relu) r = fmaxf(r, 0.f);
    dst[i] = r;
}

// ---------------- attention score vectors ----------------
__global__ void k_svec(const float* __restrict__ hh, const float* __restrict__ a,
                       float* __restrict__ s1, float* __restrict__ s2, int Hb) {
    const int n = blockIdx.x, h = blockIdx.y, b = blockIdx.z;
    const int t = threadIdx.x;
    const float v = hh[(((long)b * Hb + h) * NN + n) * FF + t];
    const float* av = a + (long)h * (2 * FF);
    float p1 = v * av[t];
    float p2 = v * av[FF + t];
    p1 = blockSum128(p1);
    p2 = blockSum128(p2);
    if (t == 0) {
        const long idx = ((long)b * Hb + h) * NN + n;
        s1[idx] = p1;
        s2[idx] = p2;
    }
}

// ---------------- masked leaky-relu softmax row (vectorized) ----------------
__global__ void k_softmax(const int* __restrict__ adj, const float* __restrict__ s1,
                          const float* __restrict__ s2, float* __restrict__ att, int Hb) {
    const int n = blockIdx.x, h = blockIdx.y, b = blockIdx.z;
    const int t = threadIdx.x;
    const int m0 = t * 4;
    const int* adjrow = adj + ((long)b * NN + n) * NN;
    const float* s2row = s2 + ((long)b * Hb + h) * NN;
    const float s1v = s1[((long)b * Hb + h) * NN + n];
    float* arow = att + (((long)b * Hb + h) * NN + n) * NN;

    const int4 aj = *(const int4*)(adjrow + m0);
    const float4 sv = *(const float4*)(s2row + m0);

    float v[4];
    {
        float e0 = s1v + sv.x; e0 = e0 > 0.f ? e0 : 0.2f * e0; v[0] = (aj.x > 0) ? e0 : NEGV;
        float e1 = s1v + sv.y; e1 = e1 > 0.f ? e1 : 0.2f * e1; v[1] = (aj.y > 0) ? e1 : NEGV;
        float e2 = s1v + sv.z; e2 = e2 > 0.f ? e2 : 0.2f * e2; v[2] = (aj.z > 0) ? e2 : NEGV;
        float e3 = s1v + sv.w; e3 = e3 > 0.f ? e3 : 0.2f * e3; v[3] = (aj.w > 0) ? e3 : NEGV;
    }
    float mx = fmaxf(fmaxf(v[0], v[1]), fmaxf(v[2], v[3]));
    mx = blockMax128(mx);
    float sum = 0.f;
#pragma unroll
    for (int j = 0; j < 4; j++) {
        v[j] = __expf(v[j] - mx);   // masked lanes underflow to exactly 0
        sum += v[j];
    }
    sum = blockSum128(sum);
    const float inv = 1.f / sum;
    *(float4*)(arow + m0) = make_float4(v[0] * inv, v[1] * inv, v[2] * inv, v[3] * inv);
}

// ---------------- residual + layernorm (+ optional relu), non-split path ----------------
__global__ void k_lnorm(const float* __restrict__ o, const float* __restrict__ res,
                        const float* __restrict__ g, const float* __restrict__ bb,
                        float* __restrict__ dst, int do_relu) {
    const int row = blockIdx.x;
    const int t = threadIdx.x;
    const float y = o[(long)row * FF + t] + res[(long)row * FF + t];
    const float mu = blockSum128(y) * (1.f / FF);
    const float d = y - mu;
    const float var = blockSum128(d * d) * (1.f / FF);
    float r = d * rsqrtf(var + 1e-5f) * g[t] + bb[t];
    if (do_relu) r = fmaxf(r, 0.f);
    dst[(long)row * FF + t] = r;
}

// ---------------- host orchestration ----------------
extern "C" void kernel_launch(void* const* d_in, const int* in_sizes, int n_in,
                              void* d_out, int out_size) {
    (void)in_sizes; (void)n_in; (void)out_size;
    const float* x       = (const float*)d_in[0];
    const int*   adj     = (const int*)  d_in[1];
    const float* Wp      = (const float*)d_in[2];
    const float* bp      = (const float*)d_in[3];
    const float* W_heads = (const float*)d_in[4];
    const float* a_heads = (const float*)d_in[5];
    const float* W_out   = (const float*)d_in[6];
    const float* a_out   = (const float*)d_in[7];
    const float* ln_g    = (const float*)d_in[8];
    const float* ln_b    = (const float*)d_in[9];
    float* out = (float*)d_out;

    float *p_h, *p_hh, *p_att, *p_multi, *p_h2, *p_att2, *p_part;
    float *p_s1, *p_s2, *p_t1, *p_t2;
    cudaGetSymbolAddress((void**)&p_h, g_h);
    cudaGetSymbolAddress((void**)&p_hh, g_hh);
    cudaGetSymbolAddress((void**)&p_att, g_att);
    cudaGetSymbolAddress((void**)&p_multi, g_multi);
    cudaGetSymbolAddress((void**)&p_h2, g_h2);
    cudaGetSymbolAddress((void**)&p_att2, g_att2);
    cudaGetSymbolAddress((void**)&p_part, g_part);
    cudaGetSymbolAddress((void**)&p_s1, g_s1);
    cudaGetSymbolAddress((void**)&p_s2, g_s2);
    cudaGetSymbolAddress((void**)&p_t1, g_t1);
    cudaGetSymbolAddress((void**)&p_t2, g_t2);

    const long long TOT = (long long)BATCH * NN * FF;   // 524288

    k_proj<<<BATCH * NN, 128>>>(x, Wp, bp, p_h);

    for (int l = 0; l < LL; l++) {
        // 1) per-head projection: hh[b,h] = h[b] @ W_heads[l,h]   (K=128)
        k_gemm_t<128, 1, 0><<<dim3(1, NN / GBM, BATCH * HH), 256>>>(
            p_h, W_heads + (long)l * HH * FF * FF, p_hh, p_part,
            NN,
            (long long)NN * FF, 0,
            0, (long long)FF * FF,
            (long long)HH * NN * FF, (long long)NN * FF,
            HH, FF, 0);

        // 2) attention score vectors
        k_svec<<<dim3(NN, HH, BATCH), 128>>>(p_hh, a_heads + (long)l * HH * 2 * FF,
                                             p_s1, p_s2, HH);

        // 3) masked softmax -> att[b,h,n,m]
        k_softmax<<<dim3(NN, HH, BATCH), 128>>>(adj, p_s1, p_s2, p_att, HH);

        // 4) att @ hh, ELU, scattered into multi[b,n,h*F+f]   (K=512)
        k_gemm_t<512, 1, 1><<<dim3(1, NN / GBM, BATCH * HH), 256>>>(
            p_att, p_hh, p_multi, p_part,
            NN,
            (long long)HH * NN * NN, (long long)NN * NN,
            (long long)HH * NN * FF, (long long)NN * FF,
            (long long)NN * HH * FF, (long long)FF,
            HH, HH * FF, 0);

        // 5+6a) out projection split-K S=4 (Kc=256) + fused reduce+svec
        k_gemm_t<256, 4, 0><<<dim3(1, (BATCH * NN) / GBM, 4), 256>>>(
            p_multi, W_out + (long)l * HH * FF * FF, p_h2, p_part,
            BATCH * NN,
            0, 0, 0, 0, 0, 0,
            1, FF, TOT);
        k_red_svec<<<BATCH * NN, 128>>>(p_part, p_h2, a_out + (long)l * 2 * FF,
                                        p_t1, p_t2, TOT);

        // 6b) single-head softmax
        k_softmax<<<dim3(NN, 1, BATCH), 128>>>(adj, p_t1, p_t2, p_att2, 1);

        // 7+8) att2 @ h2 split-K S=4 (Kc=128) + fused reduce+residual+layernorm
        k_gemm_t<128, 4, 0><<<dim3(1, NN / GBM, BATCH * 4), 256>>>(
            p_att2, p_h2, (float*)nullptr, p_part,
            NN,
            (long long)NN * NN, 0,
            (long long)NN * FF, 0,
            0, 0,
            1, FF, TOT);
        float* dst = (l == LL - 1) ? out : p_h;
        k_red_lnorm<<<BATCH * NN, 128>>>(p_part, p_h,
                                         ln_g + (long)l * FF, ln_b + (long)l * FF,
                                         dst, (l < LL - 1) ? 1 : 0, TOT);
    }
}

// round 8
// speedup vs baseline: 2.2151x; 1.0688x over previous
#include <cuda_runtime.h>
#include <cuda_bf16.h>
#include <math.h>

// ---------------- problem constants ----------------
#define BATCH 8
#define NN    512
#define DIN   64
#define HH    8
#define FF    128
#define LL    2
#define NEGV  (-9e15f)

// ---------------- scratch (device globals; no allocs) ----------------
__device__ float g_h    [BATCH * NN * FF];
__device__ float g_hh   [BATCH * HH * NN * FF];
__device__ float g_multi[BATCH * NN * HH * FF];
__device__ float g_h2   [BATCH * NN * FF];
__device__ float g_part [4 * BATCH * NN * FF];        // split-K partials
__device__ float g_s1   [BATCH * HH * NN];
__device__ float g_s2   [BATCH * HH * NN];
__device__ float g_mx   [BATCH * HH * NN];
__device__ float g_iv   [BATCH * HH * NN];
__device__ float g_t1   [BATCH * NN];
__device__ float g_t2   [BATCH * NN];

// ---------------- reductions ----------------
__device__ __forceinline__ float warpSum(float v) {
#pragma unroll
    for (int o = 16; o > 0; o >>= 1) v += __shfl_xor_sync(0xffffffffu, v, o);
    return v;
}
__device__ __forceinline__ float warpMax(float v) {
#pragma unroll
    for (int o = 16; o > 0; o >>= 1) v = fmaxf(v, __shfl_xor_sync(0xffffffffu, v, o));
    return v;
}
__device__ __forceinline__ float blockSum128(float v) {
    __shared__ float sh[4];
    v = warpSum(v);
    __syncthreads();
    if ((threadIdx.x & 31) == 0) sh[threadIdx.x >> 5] = v;
    __syncthreads();
    return sh[0] + sh[1] + sh[2] + sh[3];
}
__device__ __forceinline__ float blockMax128(float v) {
    __shared__ float sh[4];
    v = warpMax(v);
    __syncthreads();
    if ((threadIdx.x & 31) == 0) sh[threadIdx.x >> 5] = v;
    __syncthreads();
    return fmaxf(fmaxf(sh[0], sh[1]), fmaxf(sh[2], sh[3]));
}

// ---------------- tf32 RNA rounding (bit trick == cvt.rna.tf32) ----------------
__device__ __forceinline__ unsigned rtf(float f) {
    return __float_as_uint(f) + 0x1000u;   // exact-0 stays 0 after 19-bit truncation
}
__device__ __forceinline__ void mma_tf32(float c[4], const unsigned a[4], const unsigned b0, const unsigned b1) {
    asm("mma.sync.aligned.m16n8k8.row.col.f32.tf32.tf32.f32 "
        "{%0,%1,%2,%3},{%4,%5,%6,%7},{%8,%9},{%0,%1,%2,%3};"
        : "+f"(c[0]), "+f"(c[1]), "+f"(c[2]), "+f"(c[3])
        : "r"(a[0]), "r"(a[1]), "r"(a[2]), "r"(a[3]), "r"(b0), "r"(b1));
}

// att element: adj>0 ? exp(leaky(s1+s2)-mx)*inv : 0, tf32-rounded
__device__ __forceinline__ unsigned att_val(int aj, float s2v, float s1r, float mxr, float ivr) {
    float e = s1r + s2v;
    e = e > 0.f ? e : 0.2f * e;
    float r = (aj > 0) ? __expf(e - mxr) * ivr : 0.f;
    return rtf(r);
}

// ---------------- input projection ----------------
__global__ void k_proj(const float* __restrict__ x, const float* __restrict__ Wp,
                       const float* __restrict__ bp, float* __restrict__ h) {
    __shared__ float xs[DIN];
    const int row = blockIdx.x;
    const int t = threadIdx.x;
    if (t < DIN) xs[t] = x[(long)row * DIN + t];
    __syncthreads();
    float acc = bp[t];
#pragma unroll
    for (int i = 0; i < DIN; i++) acc = fmaf(xs[i], Wp[i * FF + t], acc);
    h[(long)row * FF + t] = fmaxf(acc, 0.f);
}

// ---------------- pipelined TF32 tensor-core GEMM ----------------
// C[M,128] = A[M,KC*S] @ B[KC*S,128], row-major, ldb = 128.
// Block tile 128x128, K-step 16, double-buffered smem, 8 warps 4(M)x2(N).
// blockIdx.z = (z2 * S + s). EPI: 0 none, 1 ELU, 2 plain + fused svec (s1/s2 out).
// ATT: 1 = A tile computed on the fly from attention factors (adj, s1v/s2v, mx, inv).
#define GBM 128
#define GBK 16
#define ALD 24
#define BLD 136
template <int KC, int S, int EPI, int ATT>
__global__ __launch_bounds__(256, 2)
void k_gemm_t(const float* __restrict__ A, const float* __restrict__ B,
              float* __restrict__ C, float* __restrict__ Cpart,
              int M,
              long long sAb, long long sAh,
              long long sBb, long long sBh,
              long long sCb, long long sCh,
              int Hb, int ldc, long long TOT,
              const int* __restrict__ adj,
              const float* __restrict__ s1p, const float* __restrict__ s2p,
              const float* __restrict__ mxp, const float* __restrict__ ivp,
              const float* __restrict__ avec,
              float* __restrict__ o1, float* __restrict__ o2) {
    const int zz = blockIdx.z;
    const int s = zz % S;
    const int z2 = zz / S;
    const int bz = z2 / Hb, hz = z2 % Hb;
    A += bz * sAb + hz * sAh + (long long)s * KC;
    B += bz * sBb + hz * sBh + (long long)s * KC * 128;
    C += bz * sCb + hz * sCh;
    const int bm = blockIdx.y * GBM;
    constexpr long long Kfull = (long long)KC * S;
    const int soff = s * KC;   // global k offset for ATT col indexing

    __shared__ unsigned As[2][GBM][ALD];   // [m][perm_k]
    __shared__ unsigned Bs[2][GBK][BLD];   // [k][perm_n]
    __shared__ float ash[2 * FF];          // EPI==2: attention vector
    __shared__ float sv1[GBM], sv2[GBM];   // EPI==2: cross-warp partials

    const int tid  = threadIdx.x;
    const int lane = tid & 31;
    const int wid  = tid >> 5;
    const int wm = (wid & 3) * 32;
    const int wn = (wid >> 2) * 64;
    const int q = lane & 3;
    const int g = lane >> 2;

    const int arow0 = tid >> 2;
    const int ac = tid & 3;
    const int aw0 = (ac & 1) + 8 * (ac >> 1);
    const int br = tid >> 5;
    const int bc = lane * 4;

    if (EPI == 2 && tid < 2 * FF) ash[tid] = (avec + (long long)hz * 2 * FF)[tid];

    // ATT row-constant factors for this thread's 2 staging rows
    float s1r[2], mxr[2], ivr[2];
    const int* adjA = adj;
    const float* s2A = s2p;
    if (ATT) {
        adjA = adj + (long long)bz * NN * NN;
        s2A = s2p + (long long)z2 * NN;
#pragma unroll
        for (int p = 0; p < 2; p++) {
            const long long ridx = (long long)z2 * NN + bm + arow0 + p * 64;
            s1r[p] = s1p[ridx];
            mxr[p] = mxp[ridx];
            ivr[p] = ivp[ridx];
        }
    }

    float acc[2][8][4];
#pragma unroll
    for (int i = 0; i < 2; i++)
#pragma unroll
        for (int j = 0; j < 8; j++)
#pragma unroll
            for (int r = 0; r < 4; r++) acc[i][j][r] = 0.f;

    // ---- prologue: stage tile 0 ----
    if (ATT) {
        const int mg = soff + ac * 4;
        const float4 sv = *(const float4*)(s2A + mg);
#pragma unroll
        for (int p = 0; p < 2; p++) {
            const int row = arow0 + p * 64;
            const int4 aj = *(const int4*)(adjA + (long long)(bm + row) * NN + mg);
            As[0][row][aw0 + 0] = att_val(aj.x, sv.x, s1r[p], mxr[p], ivr[p]);
            As[0][row][aw0 + 2] = att_val(aj.y, sv.y, s1r[p], mxr[p], ivr[p]);
            As[0][row][aw0 + 4] = att_val(aj.z, sv.z, s1r[p], mxr[p], ivr[p]);
            As[0][row][aw0 + 6] = att_val(aj.w, sv.w, s1r[p], mxr[p], ivr[p]);
        }
    } else {
#pragma unroll
        for (int p = 0; p < 2; p++) {
            const int row = arow0 + p * 64;
            const float4 av = *(const float4*)(A + (long long)(bm + row) * Kfull + ac * 4);
            As[0][row][aw0 + 0] = rtf(av.x);
            As[0][row][aw0 + 2] = rtf(av.y);
            As[0][row][aw0 + 4] = rtf(av.z);
            As[0][row][aw0 + 6] = rtf(av.w);
        }
    }
#pragma unroll
    for (int p = 0; p < 2; p++) {
        const int rr = br + p * 8;
        const float4 bv = *(const float4*)(B + (long long)rr * 128 + bc);
#pragma unroll
        for (int j = 0; j < 4; j++) {
            const int n = bc + j;
            const int sn = ((n >> 3) & 7) + ((n & 7) << 3) + (n & 64);
            Bs[0][rr][sn] = rtf(j == 0 ? bv.x : j == 1 ? bv.y : j == 2 ? bv.z : bv.w);
        }
    }
    __syncthreads();

    int buf = 0;
#pragma unroll 2
    for (int k0 = 0; k0 < KC; k0 += GBK) {
        const bool pre = (k0 + GBK) < KC;
        float4 pa[2], pb[2];
        int4 paj[2];
        float4 psv;
        if (pre) {
            const int kn = k0 + GBK;
            if (ATT) {
                const int mg = soff + kn + ac * 4;
                psv = *(const float4*)(s2A + mg);
#pragma unroll
                for (int p = 0; p < 2; p++)
                    paj[p] = *(const int4*)(adjA + (long long)(bm + arow0 + p * 64) * NN + mg);
            } else {
#pragma unroll
                for (int p = 0; p < 2; p++) {
                    const int row = arow0 + p * 64;
                    pa[p] = *(const float4*)(A + (long long)(bm + row) * Kfull + kn + ac * 4);
                }
            }
#pragma unroll
            for (int p = 0; p < 2; p++) {
                const int rr = br + p * 8;
                pb[p] = *(const float4*)(B + (long long)(kn + rr) * 128 + bc);
            }
        }

        // ---- compute on current buffer ----
#pragma unroll
        for (int ks = 0; ks < GBK; ks += 8) {
            const unsigned* r0 = &Bs[buf][ks + q][0];
            const unsigned* r1 = &Bs[buf][ks + q + 4][0];
            const uint4 b0a = *(const uint4*)(r0 + wn + 8 * g);
            const uint4 b0b = *(const uint4*)(r0 + wn + 8 * g + 4);
            const uint4 b1a = *(const uint4*)(r1 + wn + 8 * g);
            const uint4 b1b = *(const uint4*)(r1 + wn + 8 * g + 4);
            const unsigned bu0[8] = {b0a.x, b0a.y, b0a.z, b0a.w, b0b.x, b0b.y, b0b.z, b0b.w};
            const unsigned bu1[8] = {b1a.x, b1a.y, b1a.z, b1a.w, b1b.x, b1b.y, b1b.z, b1b.w};
            unsigned af[2][4];
#pragma unroll
            for (int mt = 0; mt < 2; mt++) {
                const int m0 = wm + mt * 16 + g;
                const uint2 a0 = *(const uint2*)&As[buf][m0][ks + 2 * q];
                const uint2 a1 = *(const uint2*)&As[buf][m0 + 8][ks + 2 * q];
                af[mt][0] = a0.x; af[mt][1] = a1.x; af[mt][2] = a0.y; af[mt][3] = a1.y;
            }
#pragma unroll
            for (int mt = 0; mt < 2; mt++)
#pragma unroll
                for (int nt = 0; nt < 8; nt++)
                    mma_tf32(acc[mt][nt], af[mt], bu0[nt], bu1[nt]);
        }

        // ---- stage next tile ----
        if (pre) {
            const int nb = buf ^ 1;
            if (ATT) {
#pragma unroll
                for (int p = 0; p < 2; p++) {
                    const int row = arow0 + p * 64;
                    As[nb][row][aw0 + 0] = att_val(paj[p].x, psv.x, s1r[p], mxr[p], ivr[p]);
                    As[nb][row][aw0 + 2] = att_val(paj[p].y, psv.y, s1r[p], mxr[p], ivr[p]);
                    As[nb][row][aw0 + 4] = att_val(paj[p].z, psv.z, s1r[p], mxr[p], ivr[p]);
                    As[nb][row][aw0 + 6] = att_val(paj[p].w, psv.w, s1r[p], mxr[p], ivr[p]);
                }
            } else {
#pragma unroll
                for (int p = 0; p < 2; p++) {
                    const int row = arow0 + p * 64;
                    As[nb][row][aw0 + 0] = rtf(pa[p].x);
                    As[nb][row][aw0 + 2] = rtf(pa[p].y);
                    As[nb][row][aw0 + 4] = rtf(pa[p].z);
                    As[nb][row][aw0 + 6] = rtf(pa[p].w);
                }
            }
#pragma unroll
            for (int p = 0; p < 2; p++) {
                const int rr = br + p * 8;
#pragma unroll
                for (int j = 0; j < 4; j++) {
                    const int n = bc + j;
                    const int sn = ((n >> 3) & 7) + ((n & 7) << 3) + (n & 64);
                    Bs[nb][rr][sn] = rtf(j == 0 ? pb[p].x : j == 1 ? pb[p].y : j == 2 ? pb[p].z : pb[p].w);
                }
            }
            __syncthreads();
            buf = nb;
        }
    }

    // ---- epilogue ----
    float p1[2][2], p2[2][2];
    if (EPI == 2) {
#pragma unroll
        for (int mt = 0; mt < 2; mt++)
#pragma unroll
            for (int hf = 0; hf < 2; hf++) { p1[mt][hf] = 0.f; p2[mt][hf] = 0.f; }
    }
#pragma unroll
    for (int mt = 0; mt < 2; mt++) {
#pragma unroll
        for (int half = 0; half < 2; half++) {
            const int row = wm + mt * 16 + g + half * 8;
            if (S == 1) {
                float* crow = C + (long long)(bm + row) * ldc;
#pragma unroll
                for (int nt = 0; nt < 8; nt++) {
                    const int col = wn + nt * 8 + 2 * q;
                    float v0 = acc[mt][nt][half * 2 + 0];
                    float v1 = acc[mt][nt][half * 2 + 1];
                    if (EPI == 1) {
                        v0 = v0 > 0.f ? v0 : (__expf(v0) - 1.f);
                        v1 = v1 > 0.f ? v1 : (__expf(v1) - 1.f);
                    }
                    if (EPI == 2) {
                        p1[mt][half] += v0 * ash[col] + v1 * ash[col + 1];
                        p2[mt][half] += v0 * ash[FF + col] + v1 * ash[FF + col + 1];
                    }
                    *(float2*)(crow + col) = make_float2(v0, v1);
                }
            } else {
                float* prow = Cpart + (long long)s * TOT + ((long long)z2 * M + bm + row) * 128;
#pragma unroll
                for (int nt = 0; nt < 8; nt++) {
                    const int col = wn + nt * 8 + 2 * q;
                    *(float2*)(prow + col) = make_float2(acc[mt][nt][half * 2 + 0],
                                                         acc[mt][nt][half * 2 + 1]);
                }
            }
        }
    }

    if (EPI == 2) {
        // quad-reduce (lanes 4g..4g+3 share a row set), then cross the 2 n-warps via smem
#pragma unroll
        for (int mt = 0; mt < 2; mt++)
#pragma unroll
            for (int hf = 0; hf < 2; hf++) {
                p1[mt][hf] += __shfl_xor_sync(0xffffffffu, p1[mt][hf], 1);
                p1[mt][hf] += __shfl_xor_sync(0xffffffffu, p1[mt][hf], 2);
                p2[mt][hf] += __shfl_xor_sync(0xffffffffu, p2[mt][hf], 1);
                p2[mt][hf] += __shfl_xor_sync(0xffffffffu, p2[mt][hf], 2);
            }
        __syncthreads();
        if ((wid >> 2) == 0 && q == 0) {
#pragma unroll
            for (int mt = 0; mt < 2; mt++)
#pragma unroll
                for (int hf = 0; hf < 2; hf++) {
                    const int r = wm + mt * 16 + hf * 8 + g;
                    sv1[r] = p1[mt][hf];
                    sv2[r] = p2[mt][hf];
                }
        }
        __syncthreads();
        if ((wid >> 2) == 1 && q == 0) {
#pragma unroll
            for (int mt = 0; mt < 2; mt++)
#pragma unroll
                for (int hf = 0; hf < 2; hf++) {
                    const int r = wm + mt * 16 + hf * 8 + g;
                    const long long oidx = (long long)z2 * NN + bm + r;
                    o1[oidx] = sv1[r] + p1[mt][hf];
                    o2[oidx] = sv2[r] + p2[mt][hf];
                }
        }
    }
}

// ---------------- row stats: mx and 1/sum of masked leaky-softmax ----------------
__global__ void k_stats(const int* __restrict__ adj, const float* __restrict__ s1,
                        const float* __restrict__ s2, float* __restrict__ mx,
                        float* __restrict__ iv, int Hb) {
    const int n = blockIdx.x, h = blockIdx.y, b = blockIdx.z;
    const int t = threadIdx.x;
    const int m0 = t * 4;
    const int* adjrow = adj + ((long)b * NN + n) * NN;
    const long idx = ((long)b * Hb + h) * NN + n;
    const float* s2row = s2 + ((long)b * Hb + h) * NN;
    const float s1v = s1[idx];

    const int4 aj = *(const int4*)(adjrow + m0);
    const float4 sv = *(const float4*)(s2row + m0);

    float v[4];
    {
        float e0 = s1v + sv.x; e0 = e0 > 0.f ? e0 : 0.2f * e0; v[0] = (aj.x > 0) ? e0 : NEGV;
        float e1 = s1v + sv.y; e1 = e1 > 0.f ? e1 : 0.2f * e1; v[1] = (aj.y > 0) ? e1 : NEGV;
        float e2 = s1v + sv.z; e2 = e2 > 0.f ? e2 : 0.2f * e2; v[2] = (aj.z > 0) ? e2 : NEGV;
        float e3 = s1v + sv.w; e3 = e3 > 0.f ? e3 : 0.2f * e3; v[3] = (aj.w > 0) ? e3 : NEGV;
    }
    float mv = fmaxf(fmaxf(v[0], v[1]), fmaxf(v[2], v[3]));
    mv = blockMax128(mv);
    float sum = 0.f;
#pragma unroll
    for (int j = 0; j < 4; j++) sum += __expf(v[j] - mv);
    sum = blockSum128(sum);
    if (t == 0) {
        mx[idx] = mv;
        iv[idx] = 1.f / sum;
    }
}

// ---------------- fused split-K reduce + svec (h2 + t1/t2) ----------------
__global__ void k_red_svec(const float* __restrict__ part, float* __restrict__ h2,
                           const float* __restrict__ a, float* __restrict__ t1,
                           float* __restrict__ t2, long long TOT) {
    const int row = blockIdx.x;
    const int t = threadIdx.x;
    const long long i = (long long)row * FF + t;
    float v = part[i] + (part[TOT + i] + part[2 * TOT + i] + part[3 * TOT + i]);
    h2[i] = v;
    float p1 = v * a[t];
    float p2 = v * a[FF + t];
    p1 = blockSum128(p1);
    p2 = blockSum128(p2);
    if (t == 0) {
        t1[row] = p1;
        t2[row] = p2;
    }
}

// ---------------- fused split-K reduce + residual + layernorm (+relu) ----------------
__global__ void k_red_lnorm(const float* __restrict__ part, const float* __restrict__ res,
                            const float* __restrict__ g, const float* __restrict__ bb,
                            float* __restrict__ dst, int do_relu, long long TOT) {
    const int row = blockIdx.x;
    const int t = threadIdx.x;
    const long long i = (long long)row * FF + t;
    const float o = part[i] + (part[TOT + i] + part[2 * TOT + i] + part[3 * TOT + i]);
    const float y = o + res[i];
    const float mu = blockSum128(y) * (1.f / FF);
    const float d = y - mu;
    const float var = blockSum128(d * d) * (1.f / FF);
    float r = d * rsqrtf(var + 1e-5f) * g[t] + bb[t];
    if (do_relu) r = fmaxf(r, 0.f);
    dst[i] = r;
}

// ---------------- host orchestration ----------------
extern "C" void kernel_launch(void* const* d_in, const int* in_sizes, int n_in,
                              void* d_out, int out_size) {
    (void)in_sizes; (void)n_in; (void)out_size;
    const float* x       = (const float*)d_in[0];
    const int*   adj     = (const int*)  d_in[1];
    const float* Wp      = (const float*)d_in[2];
    const float* bp      = (const float*)d_in[3];
    const float* W_heads = (const float*)d_in[4];
    const float* a_heads = (const float*)d_in[5];
    const float* W_out   = (const float*)d_in[6];
    const float* a_out   = (const float*)d_in[7];
    const float* ln_g    = (const float*)d_in[8];
    const float* ln_b    = (const float*)d_in[9];
    float* out = (float*)d_out;

    float *p_h, *p_hh, *p_multi, *p_h2, *p_part;
    float *p_s1, *p_s2, *p_mx, *p_iv, *p_t1, *p_t2;
    cudaGetSymbolAddress((void**)&p_h, g_h);
    cudaGetSymbolAddress((void**)&p_hh, g_hh);
    cudaGetSymbolAddress((void**)&p_multi, g_multi);
    cudaGetSymbolAddress((void**)&p_h2, g_h2);
    cudaGetSymbolAddress((void**)&p_part, g_part);
    cudaGetSymbolAddress((void**)&p_s1, g_s1);
    cudaGetSymbolAddress((void**)&p_s2, g_s2);
    cudaGetSymbolAddress((void**)&p_mx, g_mx);
    cudaGetSymbolAddress((void**)&p_iv, g_iv);
    cudaGetSymbolAddress((void**)&p_t1, g_t1);
    cudaGetSymbolAddress((void**)&p_t2, g_t2);

    const long long TOT = (long long)BATCH * NN * FF;   // 524288

    k_proj<<<BATCH * NN, 128>>>(x, Wp, bp, p_h);

    for (int l = 0; l < LL; l++) {
        // 1) per-head projection + fused svec: hh = h @ W_heads[l,h]; s1/s2 = hh . a
        k_gemm_t<128, 1, 2, 0><<<dim3(1, NN / GBM, BATCH * HH), 256>>>(
            p_h, W_heads + (long)l * HH * FF * FF, p_hh, p_part,
            NN,
            (long long)NN * FF, 0,
            0, (long long)FF * FF,
            (long long)HH * NN * FF, (long long)NN * FF,
            HH, FF, 0,
            nullptr, nullptr, nullptr, nullptr, nullptr,
            a_heads + (long)l * HH * 2 * FF, p_s1, p_s2);

        // 2) softmax row stats (mx, 1/sum)
        k_stats<<<dim3(NN, HH, BATCH), 128>>>(adj, p_s1, p_s2, p_mx, p_iv, HH);

        // 3) fused (softmax ∘ att) @ hh, ELU, scattered into multi[b,n,h*F+f]
        k_gemm_t<512, 1, 1, 1><<<dim3(1, NN / GBM, BATCH * HH), 256>>>(
            nullptr, p_hh, p_multi, p_part,
            NN,
            0, 0,
            (long long)HH * NN * FF, (long long)NN * FF,
            (long long)NN * HH * FF, (long long)FF,
            HH, HH * FF, 0,
            adj, p_s1, p_s2, p_mx, p_iv,
            nullptr, nullptr, nullptr);

        // 4) out projection split-K S=4 + fused reduce+svec
        k_gemm_t<256, 4, 0, 0><<<dim3(1, (BATCH * NN) / GBM, 4), 256>>>(
            p_multi, W_out + (long)l * HH * FF * FF, p_h2, p_part,
            BATCH * NN,
            0, 0, 0, 0, 0, 0,
            1, FF, TOT,
            nullptr, nullptr, nullptr, nullptr, nullptr,
            nullptr, nullptr, nullptr);
        k_red_svec<<<BATCH * NN, 128>>>(p_part, p_h2, a_out + (long)l * 2 * FF,
                                        p_t1, p_t2, TOT);

        // 5) single-head stats
        k_stats<<<dim3(NN, 1, BATCH), 128>>>(adj, p_t1, p_t2, p_mx, p_iv, 1);

        // 6) fused (softmax ∘ att2) @ h2 split-K S=4 + fused reduce+residual+layernorm
        k_gemm_t<128, 4, 0, 1><<<dim3(1, NN / GBM, BATCH * 4), 256>>>(
            nullptr, p_h2, nullptr, p_part,
            NN,
            0, 0,
            (long long)NN * FF, 0,
            0, 0,
            1, FF, TOT,
            adj, p_t1, p_t2, p_mx, p_iv,
            nullptr, nullptr, nullptr);
        float* dst = (l == LL - 1) ? out : p_h;
        k_red_lnorm<<<BATCH * NN, 128>>>(p_part, p_h,
                                         ln_g + (long)l * FF, ln_b + (long)l * FF,
                                         dst, (l < LL - 1) ? 1 : 0, TOT);
    }
}